// round 6
// baseline (speedup 1.0000x reference)
#include <cuda_runtime.h>
#include <cuda_bf16.h>
#include <cstdint>
#include <math.h>

#define BH 16
#define LSEQ 2048
#define DH 64
#define OUT_ELE (LSEQ * DH * BH)
#define ATT_ELE ((size_t)BH * LSEQ * LSEQ)

__device__ __nv_bfloat16 g_Qh[BH * LSEQ * DH];
__device__ __nv_bfloat16 g_Ql[BH * LSEQ * DH];
__device__ __nv_bfloat16 g_Kh[BH * LSEQ * DH];
__device__ __nv_bfloat16 g_Kl[BH * LSEQ * DH];
__device__ __nv_bfloat16 g_Vth[BH * DH * LSEQ];
__device__ __nv_bfloat16 g_Vtl[BH * DH * LSEQ];

__device__ __forceinline__ uint32_t smem_u32(const void* p) {
    uint32_t a;
    asm("{ .reg .u64 t; cvta.to.shared.u64 t, %1; cvt.u32.u64 %0, t; }" : "=r"(a) : "l"(p));
    return a;
}
__device__ __forceinline__ void ldsm4(uint32_t* r, uint32_t addr) {
    asm volatile("ldmatrix.sync.aligned.m8n8.x4.shared.b16 {%0,%1,%2,%3}, [%4];"
                 : "=r"(r[0]), "=r"(r[1]), "=r"(r[2]), "=r"(r[3]) : "r"(addr));
}
__device__ __forceinline__ void mma16816(float* c, const uint32_t* a, uint32_t b0, uint32_t b1) {
    asm volatile("mma.sync.aligned.m16n8k16.row.col.f32.bf16.bf16.f32 "
                 "{%0,%1,%2,%3}, {%4,%5,%6,%7}, {%8,%9}, {%0,%1,%2,%3};"
                 : "+f"(c[0]), "+f"(c[1]), "+f"(c[2]), "+f"(c[3])
                 : "r"(a[0]), "r"(a[1]), "r"(a[2]), "r"(a[3]), "r"(b0), "r"(b1));
}
__device__ __forceinline__ void split2(float a, float b, uint32_t& hi, uint32_t& lo) {
    __nv_bfloat16 ah = __float2bfloat16(a), bh = __float2bfloat16(b);
    float al = a - __bfloat162float(ah);
    float bl = b - __bfloat162float(bh);
    __nv_bfloat162 H; H.x = ah; H.y = bh;
    __nv_bfloat162 L; L.x = __float2bfloat16(al); L.y = __float2bfloat16(bl);
    hi = *reinterpret_cast<uint32_t*>(&H);
    lo = *reinterpret_cast<uint32_t*>(&L);
}
__device__ __forceinline__ void cpasync16(uint32_t dst, const void* src) {
    asm volatile("cp.async.cg.shared.global [%0], [%1], 16;" :: "r"(dst), "l"(src));
}
#define CP_COMMIT() asm volatile("cp.async.commit_group;" ::: "memory")
#define CP_WAIT1()  asm volatile("cp.async.wait_group 1;" ::: "memory")
#define CP_WAIT0()  asm volatile("cp.async.wait_group 0;" ::: "memory")
__device__ __forceinline__ uint32_t prmt_hi(uint32_t a, uint32_t b) {
    uint32_t d;
    asm("prmt.b32 %0, %1, %2, 0x7632;" : "=r"(d) : "r"(a), "r"(b));
    return d;
}
__device__ __forceinline__ uint32_t cvt_bf16x2(float hi, float lo) {
    uint32_t d;
    asm("cvt.rn.bf16x2.f32 %0, %1, %2;" : "=r"(d) : "f"(hi), "f"(lo));
    return d;
}

// ---------------- Prepass ----------------
__global__ void prep_qk(const float* __restrict__ q, const float* __restrict__ k) {
    int blk = blockIdx.x;
    const float* src = (blk < 2048) ? q : k;
    int idx = (blk & 2047) * 256 + threadIdx.x;
    float4 x = ((const float4*)src)[idx];
    uint32_t h0, l0, h1, l1;
    if (blk < 2048) { x.x *= 0.125f; x.y *= 0.125f; x.z *= 0.125f; x.w *= 0.125f; }
    split2(x.x, x.y, h0, l0);
    split2(x.z, x.w, h1, l1);
    if (blk < 2048) {
        ((uint2*)g_Qh)[idx] = make_uint2(h0, h1);
        ((uint2*)g_Ql)[idx] = make_uint2(l0, l1);
    } else {
        ((uint2*)g_Kh)[idx] = make_uint2(h0, h1);
        ((uint2*)g_Kl)[idx] = make_uint2(l0, l1);
    }
}
__global__ void prep_v(const float* __restrict__ v) {
    __shared__ float vs[128 * 65];
    const int b = blockIdx.x >> 4, st = blockIdx.x & 15, tid = threadIdx.x;
    const float4* vp = (const float4*)(v + ((size_t)(b * LSEQ + st * 128)) * DH);
#pragma unroll
    for (int it = 0; it < 8; ++it) {
        int fi = it * 256 + tid;
        int s = fi >> 4, d4 = fi & 15;
        float4 x = vp[fi];
        vs[s * 65 + d4 * 4 + 0] = x.x;
        vs[s * 65 + d4 * 4 + 1] = x.y;
        vs[s * 65 + d4 * 4 + 2] = x.z;
        vs[s * 65 + d4 * 4 + 3] = x.w;
    }
    __syncthreads();
#pragma unroll
    for (int it = 0; it < 4; ++it) {
        int fo = it * 256 + tid;
        int d = fo >> 4, cu = fo & 15;
        float vv[8];
#pragma unroll
        for (int j = 0; j < 8; ++j) vv[j] = vs[(cu * 8 + j) * 65 + d];
        uint32_t hw[4], lw[4];
#pragma unroll
        for (int j = 0; j < 4; ++j) split2(vv[2 * j], vv[2 * j + 1], hw[j], lw[j]);
        size_t o = ((size_t)(b * DH + d)) * LSEQ + st * 128 + cu * 8;
        *(uint4*)(g_Vth + o) = make_uint4(hw[0], hw[1], hw[2], hw[3]);
        *(uint4*)(g_Vtl + o) = make_uint4(lw[0], lw[1], lw[2], lw[3]);
    }
}

// ---------------- Fused attention (512 threads, 16 warps) ----------------
// Q 0..32K | K bufs 32K..128K (3x32K, hi+lo) | V bufs 128K..224K (3x32K)
// aliases: SRED -> K2 region (between sweeps), ored -> Q region (epilogue)
#define SQH 0
#define SQL 16384
#define SKB(i) (32768 + (i) * 32768)
#define SVB(i) (131072 + (i) * 32768)
#define SRED 98304
#define SMEM_TOT 229376

__global__ void __launch_bounds__(512, 1)
sdpa_fused(float* __restrict__ attn, float* __restrict__ lattn, float* __restrict__ outp) {
    extern __shared__ char sm[];
    const uint32_t sb = smem_u32(sm);
    const int tid = threadIdx.x, lane = tid & 31, w = tid >> 5;
    const int wm = w >> 1, wn = w & 1;          // 8 row-groups x 2 col-halves
    const int b = blockIdx.y, qbase = blockIdx.x * 128;

    const int arow = lane & 15, achk = lane >> 4;
    const int brow = ((lane >> 4) << 3) + (lane & 7), bch = (lane >> 3) & 1;
    const int qrow = wm * 16 + arow;

    const char* kh_base = (const char*)(g_Kh + (size_t)b * LSEQ * DH);
    const char* kl_base = (const char*)(g_Kl + (size_t)b * LSEQ * DH);
    const char* vh_base = (const char*)(g_Vth + (size_t)b * DH * LSEQ);
    const char* vl_base = (const char*)(g_Vtl + (size_t)b * DH * LSEQ);

#define LOAD_K(buf, t) do {                                                    \
        const char* _sh = kh_base + (size_t)(t) * 16384;                       \
        const char* _sl = kl_base + (size_t)(t) * 16384;                       \
        _Pragma("unroll")                                                      \
        for (int r = 0; r < 2; ++r) {                                          \
            int fo = r * 512 + tid;                                            \
            int row = fo >> 3, cu = fo & 7;                                    \
            uint32_t off = (uint32_t)row * 128 + ((cu ^ (row & 7)) << 4);      \
            cpasync16(sb + (buf) + off, _sh + fo * 16);                        \
            cpasync16(sb + (buf) + 16384 + off, _sl + fo * 16);                \
        }                                                                      \
    } while (0)

#define LOAD_V(buf, t) do {                                                    \
        const char* _sh = vh_base + (size_t)(t) * 256;                         \
        const char* _sl = vl_base + (size_t)(t) * 256;                         \
        _Pragma("unroll")                                                      \
        for (int r = 0; r < 2; ++r) {                                          \
            int fo = r * 512 + tid;                                            \
            int row = fo >> 4, cu = fo & 15;                                   \
            uint32_t off = (uint32_t)row * 256 + ((cu ^ (row & 15)) << 4);     \
            size_t sof = (size_t)row * (LSEQ * 2) + cu * 16;                   \
            cpasync16(sb + (buf) + off, _sh + sof);                            \
            cpasync16(sb + (buf) + 16384 + off, _sl + sof);                    \
        }                                                                      \
    } while (0)

    // ---- sweep1 prologue: group0 = Q + K0, group1 = K1 ----
    {
        const char* qh = (const char*)(g_Qh + (size_t)(b * LSEQ + qbase) * DH);
        const char* ql = (const char*)(g_Ql + (size_t)(b * LSEQ + qbase) * DH);
#pragma unroll
        for (int r = 0; r < 2; ++r) {
            int fo = r * 512 + tid;
            int row = fo >> 3, cu = fo & 7;
            uint32_t off = (uint32_t)row * 128 + ((cu ^ (row & 7)) << 4);
            cpasync16(sb + SQH + off, qh + fo * 16);
            cpasync16(sb + SQL + off, ql + fo * 16);
        }
        LOAD_K(SKB(0), 0);
        CP_COMMIT();
        LOAD_K(SKB(1), 1);
        CP_COMMIT();
    }

    // QK: paired-p ordering (accumulator reuse distance 4). Q frags passed in.
#define QK_TILE(c, kb, AQH, AQL) do {                                          \
        _Pragma("unroll")                                                      \
        for (int nt = 0; nt < 8; ++nt) {                                       \
            c[nt][0] = 0.f; c[nt][1] = 0.f; c[nt][2] = 0.f; c[nt][3] = 0.f;    \
        }                                                                      \
        _Pragma("unroll")                                                      \
        for (int ks = 0; ks < 4; ++ks) {                                       \
            _Pragma("unroll")                                                  \
            for (int pp = 0; pp < 4; pp += 2) {                                \
                int row0 = wn * 64 + pp * 16 + brow;                           \
                int row1 = row0 + 16;                                          \
                uint32_t ad0 = sb + (kb) + row0 * 128 +                        \
                               (((ks * 2 + bch) ^ (row0 & 7)) << 4);           \
                uint32_t ad1 = sb + (kb) + row1 * 128 +                        \
                               (((ks * 2 + bch) ^ (row1 & 7)) << 4);           \
                uint32_t bh0[4], bh1[4], bl0[4], bl1[4];                       \
                ldsm4(bh0, ad0);                                               \
                ldsm4(bh1, ad1);                                               \
                ldsm4(bl0, ad0 + 16384);                                       \
                ldsm4(bl1, ad1 + 16384);                                       \
                mma16816(c[2*pp],   AQH[ks], bh0[0], bh0[1]);                  \
                mma16816(c[2*pp+1], AQH[ks], bh0[2], bh0[3]);                  \
                mma16816(c[2*pp+2], AQH[ks], bh1[0], bh1[1]);                  \
                mma16816(c[2*pp+3], AQH[ks], bh1[2], bh1[3]);                  \
                mma16816(c[2*pp],   AQH[ks], bl0[0], bl0[1]);                  \
                mma16816(c[2*pp+1], AQH[ks], bl0[2], bl0[3]);                  \
                mma16816(c[2*pp+2], AQH[ks], bl1[0], bl1[1]);                  \
                mma16816(c[2*pp+3], AQH[ks], bl1[2], bl1[3]);                  \
                mma16816(c[2*pp],   AQL[ks], bh0[0], bh0[1]);                  \
                mma16816(c[2*pp+1], AQL[ks], bh0[2], bh0[3]);                  \
                mma16816(c[2*pp+2], AQL[ks], bh1[0], bh1[1]);                  \
                mma16816(c[2*pp+3], AQL[ks], bh1[2], bh1[3]);                  \
            }                                                                  \
        }                                                                      \
    } while (0)

    float mrun[2] = {-INFINITY, -INFINITY}, lrun[2] = {0.f, 0.f};

    // ================= Sweep 1: stats =================
    {
        uint32_t aQh[4][4], aQl[4][4];
        for (int t = 0; t < 16; ++t) {
            if (t < 15) { CP_WAIT1(); } else { CP_WAIT0(); }
            __syncthreads();
            if (t + 2 < 16) {
                LOAD_K(SKB((t + 2) % 3), t + 2);
                CP_COMMIT();
            }
            if (t == 0) {
#pragma unroll
                for (int ks = 0; ks < 4; ++ks) {
                    uint32_t qad = sb + qrow * 128 + (((ks * 2 + achk) ^ (qrow & 7)) << 4);
                    ldsm4(aQh[ks], qad);
                    ldsm4(aQl[ks], qad + 16384);
                }
            }
            float c[8][4];
            QK_TILE(c, SKB(t % 3), aQh, aQl);
#pragma unroll
            for (int h = 0; h < 2; ++h) {
                float mx = mrun[h];
#pragma unroll
                for (int nt = 0; nt < 8; ++nt)
                    mx = fmaxf(mx, fmaxf(c[nt][2 * h], c[nt][2 * h + 1]));
                float sum = 0.f;
#pragma unroll
                for (int nt = 0; nt < 8; ++nt)
                    sum += __expf(c[nt][2 * h] - mx) + __expf(c[nt][2 * h + 1] - mx);
                lrun[h] = lrun[h] * __expf(mrun[h] - mx) + sum;
                mrun[h] = mx;
            }
        }
    }

    // quad reduce, publish per (row, wn) to SRED (aliases K2; sweep1 done with it)
#pragma unroll
    for (int h = 0; h < 2; ++h) {
        float m = mrun[h], l = lrun[h];
#pragma unroll
        for (int o = 1; o <= 2; o <<= 1) {
            float om = __shfl_xor_sync(0xffffffffu, m, o);
            float ol = __shfl_xor_sync(0xffffffffu, l, o);
            float nm = fmaxf(m, om);
            l = l * __expf(m - nm) + ol * __expf(om - nm);
            m = nm;
        }
        if ((lane & 3) == 0) {
            int row = wm * 16 + (lane >> 2) + 8 * h;
            *(float2*)(sm + SRED + (row * 2 + wn) * 8) = make_float2(m, l);
        }
    }
    __syncthreads();
    float lz0, lz1;
    {
        int r0 = wm * 16 + (lane >> 2);
        float2 a0 = *(float2*)(sm + SRED + (r0 * 2) * 8);
        float2 a1 = *(float2*)(sm + SRED + (r0 * 2 + 1) * 8);
        float m = fmaxf(a0.x, a1.x);
        lz0 = m + logf(a0.y * __expf(a0.x - m) + a1.y * __expf(a1.x - m));
        int r1 = r0 + 8;
        float2 b0 = *(float2*)(sm + SRED + (r1 * 2) * 8);
        float2 b1 = *(float2*)(sm + SRED + (r1 * 2 + 1) * 8);
        float m2 = fmaxf(b0.x, b1.x);
        lz1 = m2 + logf(b0.y * __expf(b0.x - m2) + b1.y * __expf(b1.x - m2));
    }

    // ================= Sweep 2: emit + PV (k-split across wn) =================
    float o[8][4];
#pragma unroll
    for (int g = 0; g < 8; ++g)
#pragma unroll
        for (int j = 0; j < 4; ++j) o[g][j] = 0.f;

    LOAD_K(SKB(0), 0);
    LOAD_V(SVB(0), 0);
    CP_COMMIT();
    LOAD_K(SKB(1), 1);
    LOAD_V(SVB(1), 1);
    CP_COMMIT();

    float* aRow = attn + ((size_t)(b * LSEQ + qbase + wm * 16 + (lane >> 2))) * LSEQ +
                  wn * 64 + (lane & 3) * 2;
    float* lRow = lattn + ((size_t)(b * LSEQ + qbase + wm * 16 + (lane >> 2))) * LSEQ +
                  wn * 64 + (lane & 3) * 2;

    for (int t = 0; t < 16; ++t) {
        if (t < 15) { CP_WAIT1(); } else { CP_WAIT0(); }
        __syncthreads();
        if (t + 2 < 16) {
            LOAD_K(SKB((t + 2) % 3), t + 2);
            LOAD_V(SVB((t + 2) % 3), t + 2);
            CP_COMMIT();
        }

        uint32_t aQh[4][4], aQl[4][4];
#pragma unroll
        for (int ks = 0; ks < 4; ++ks) {
            uint32_t qad = sb + qrow * 128 + (((ks * 2 + achk) ^ (qrow & 7)) << 4);
            ldsm4(aQh[ks], qad);
            ldsm4(aQl[ks], qad + 16384);
        }
        float c[8][4];
        QK_TILE(c, SKB(t % 3), aQh, aQl);

        // per kc-chunk: convert + stores interleaved with PV mma bursts
        const uint32_t vb = sb + SVB(t % 3);
        float* aT = aRow + t * 128;
        float* lT = lRow + t * 128;
#pragma unroll
        for (int kc = 0; kc < 4; ++kc) {
            uint32_t aPh[4], aPl[4];
#pragma unroll
            for (int qq = 0; qq < 2; ++qq) {
                const int nt = 2 * kc + qq;
                float la0 = c[nt][0] - lz0, la1 = c[nt][1] - lz0;
                float la2 = c[nt][2] - lz1, la3 = c[nt][3] - lz1;
                float p0 = __expf(la0), p1 = __expf(la1);
                float p2 = __expf(la2), p3 = __expf(la3);
                *(float2*)(aT + nt * 8) = make_float2(p0, p1);
                *(float2*)(aT + 8 * LSEQ + nt * 8) = make_float2(p2, p3);
                *(float2*)(lT + nt * 8) = make_float2(la0, la1);
                *(float2*)(lT + 8 * LSEQ + nt * 8) = make_float2(la2, la3);
                uint32_t u0 = __float_as_uint(p0), u1 = __float_as_uint(p1);
                uint32_t u2 = __float_as_uint(p2), u3 = __float_as_uint(p3);
                aPh[qq * 2 + 0] = prmt_hi(u0, u1);
                aPh[qq * 2 + 1] = prmt_hi(u2, u3);
                aPl[qq * 2 + 0] = cvt_bf16x2(p1 - __uint_as_float(u1 & 0xFFFF0000u),
                                             p0 - __uint_as_float(u0 & 0xFFFF0000u));
                aPl[qq * 2 + 1] = cvt_bf16x2(p3 - __uint_as_float(u3 & 0xFFFF0000u),
                                             p2 - __uint_as_float(u2 & 0xFFFF0000u));
            }
            // PV burst for this kc: paired g2, reuse distance 4
#pragma unroll
            for (int gg = 0; gg < 4; gg += 2) {
                int row0 = gg * 16 + brow;
                int row1 = row0 + 16;
                uint32_t ad0 = vb + row0 * 256 + (((wn * 8 + kc * 2 + bch) ^ (row0 & 15)) << 4);
                uint32_t ad1 = vb + row1 * 256 + (((wn * 8 + kc * 2 + bch) ^ (row1 & 15)) << 4);
                uint32_t vh0[4], vh1[4], vl0[4], vl1[4];
                ldsm4(vh0, ad0);
                ldsm4(vh1, ad1);
                ldsm4(vl0, ad0 + 16384);
                ldsm4(vl1, ad1 + 16384);
                mma16816(o[2*gg],   aPh, vh0[0], vh0[1]);
                mma16816(o[2*gg+1], aPh, vh0[2], vh0[3]);
                mma16816(o[2*gg+2], aPh, vh1[0], vh1[1]);
                mma16816(o[2*gg+3], aPh, vh1[2], vh1[3]);
                mma16816(o[2*gg],   aPh, vl0[0], vl0[1]);
                mma16816(o[2*gg+1], aPh, vl0[2], vl0[3]);
                mma16816(o[2*gg+2], aPh, vl1[0], vl1[1]);
                mma16816(o[2*gg+3], aPh, vl1[2], vl1[3]);
                mma16816(o[2*gg],   aPl, vh0[0], vh0[1]);
                mma16816(o[2*gg+1], aPl, vh0[2], vh0[3]);
                mma16816(o[2*gg+2], aPl, vh1[0], vh1[1]);
                mma16816(o[2*gg+3], aPl, vh1[2], vh1[3]);
            }
        }
    }

    // ---- epilogue: reduce wn partials via smem (aliases Q region), write output ----
    __syncthreads();
    float* ored = (float*)sm;
    if (wn == 1) {
#pragma unroll
        for (int nt = 0; nt < 8; ++nt) {
            int col = nt * 8 + (lane & 3) * 2;
            *(float2*)(ored + (wm * 16 + (lane >> 2)) * 64 + col) = make_float2(o[nt][0], o[nt][1]);
            *(float2*)(ored + (wm * 16 + (lane >> 2) + 8) * 64 + col) = make_float2(o[nt][2], o[nt][3]);
        }
    }
    __syncthreads();
    if (wn == 0) {
        int qr = qbase + wm * 16 + (lane >> 2);
        float* dp = outp + (size_t)qr * (DH * BH) + b * DH + (lane & 3) * 2;
#pragma unroll
        for (int nt = 0; nt < 8; ++nt) {
            int col = nt * 8 + (lane & 3) * 2;
            float2 r0 = *(float2*)(ored + (wm * 16 + (lane >> 2)) * 64 + col);
            float2 r1 = *(float2*)(ored + (wm * 16 + (lane >> 2) + 8) * 64 + col);
            *(float2*)(dp + nt * 8) = make_float2(o[nt][0] + r0.x, o[nt][1] + r0.y);
            *(float2*)(dp + 8 * (DH * BH) + nt * 8) = make_float2(o[nt][2] + r1.x, o[nt][3] + r1.y);
        }
    }
}

extern "C" void kernel_launch(void* const* d_in, const int* in_sizes, int n_in,
                              void* d_out, int out_size) {
    const float* q = (const float*)d_in[0];
    const float* k = (const float*)d_in[1];
    const float* v = (const float*)d_in[2];

    float* outp = (float*)d_out;
    float* attn = outp + OUT_ELE;
    float* lattn = attn + ATT_ELE;

    cudaFuncSetAttribute(sdpa_fused, cudaFuncAttributeMaxDynamicSharedMemorySize, SMEM_TOT);

    prep_qk<<<4096, 256>>>(q, k);
    prep_v<<<256, 256>>>(v);

    dim3 grid(LSEQ / 128, BH);
    sdpa_fused<<<grid, 512, SMEM_TOT>>>(attn, lattn, outp);
}

// round 9
// speedup vs baseline: 1.0351x; 1.0351x over previous
#include <cuda_runtime.h>
#include <cuda_bf16.h>
#include <cstdint>
#include <math.h>

#define BH 16
#define LSEQ 2048
#define DH 64
#define OUT_ELE (LSEQ * DH * BH)
#define ATT_ELE ((size_t)BH * LSEQ * LSEQ)

__device__ __nv_bfloat16 g_Qh[BH * LSEQ * DH];
__device__ __nv_bfloat16 g_Ql[BH * LSEQ * DH];
__device__ __nv_bfloat16 g_Kh[BH * LSEQ * DH];
__device__ __nv_bfloat16 g_Kl[BH * LSEQ * DH];
__device__ __nv_bfloat16 g_Vth[BH * DH * LSEQ];
__device__ __nv_bfloat16 g_Vtl[BH * DH * LSEQ];

__device__ __forceinline__ uint32_t smem_u32(const void* p) {
    uint32_t a;
    asm("{ .reg .u64 t; cvta.to.shared.u64 t, %1; cvt.u32.u64 %0, t; }" : "=r"(a) : "l"(p));
    return a;
}
__device__ __forceinline__ void ldsm4(uint32_t* r, uint32_t addr) {
    asm volatile("ldmatrix.sync.aligned.m8n8.x4.shared.b16 {%0,%1,%2,%3}, [%4];"
                 : "=r"(r[0]), "=r"(r[1]), "=r"(r[2]), "=r"(r[3]) : "r"(addr));
}
__device__ __forceinline__ void mma16816(float* c, const uint32_t* a, uint32_t b0, uint32_t b1) {
    asm volatile("mma.sync.aligned.m16n8k16.row.col.f32.bf16.bf16.f32 "
                 "{%0,%1,%2,%3}, {%4,%5,%6,%7}, {%8,%9}, {%0,%1,%2,%3};"
                 : "+f"(c[0]), "+f"(c[1]), "+f"(c[2]), "+f"(c[3])
                 : "r"(a[0]), "r"(a[1]), "r"(a[2]), "r"(a[3]), "r"(b0), "r"(b1));
}
__device__ __forceinline__ void split2(float a, float b, uint32_t& hi, uint32_t& lo) {
    __nv_bfloat16 ah = __float2bfloat16(a), bh = __float2bfloat16(b);
    float al = a - __bfloat162float(ah);
    float bl = b - __bfloat162float(bh);
    __nv_bfloat162 H; H.x = ah; H.y = bh;
    __nv_bfloat162 L; L.x = __float2bfloat16(al); L.y = __float2bfloat16(bl);
    hi = *reinterpret_cast<uint32_t*>(&H);
    lo = *reinterpret_cast<uint32_t*>(&L);
}
__device__ __forceinline__ void cpasync16(uint32_t dst, const void* src) {
    asm volatile("cp.async.cg.shared.global [%0], [%1], 16;" :: "r"(dst), "l"(src));
}
#define CP_COMMIT() asm volatile("cp.async.commit_group;" ::: "memory")
#define CP_WAIT0()  asm volatile("cp.async.wait_group 0;" ::: "memory")
__device__ __forceinline__ uint32_t prmt_hi(uint32_t a, uint32_t b) {
    uint32_t d;
    asm("prmt.b32 %0, %1, %2, 0x7632;" : "=r"(d) : "r"(a), "r"(b));
    return d;
}
__device__ __forceinline__ uint32_t cvt_bf16x2(float hi, float lo) {
    uint32_t d;
    asm("cvt.rn.bf16x2.f32 %0, %1, %2;" : "=r"(d) : "f"(hi), "f"(lo));
    return d;
}

// ---------------- Prepass ----------------
__global__ void prep_q(const float* __restrict__ q) {
    int idx = blockIdx.x * 256 + threadIdx.x;
    float4 x = ((const float4*)q)[idx];
    x.x *= 0.125f; x.y *= 0.125f; x.z *= 0.125f; x.w *= 0.125f;
    uint32_t h0, l0, h1, l1;
    split2(x.x, x.y, h0, l0);
    split2(x.z, x.w, h1, l1);
    ((uint2*)g_Qh)[idx] = make_uint2(h0, h1);
    ((uint2*)g_Ql)[idx] = make_uint2(l0, l1);
}
__global__ void prep_k(const float* __restrict__ k) {
    int idx = blockIdx.x * 256 + threadIdx.x;
    float4 x = ((const float4*)k)[idx];
    uint32_t h0, l0, h1, l1;
    split2(x.x, x.y, h0, l0);
    split2(x.z, x.w, h1, l1);
    ((uint2*)g_Kh)[idx] = make_uint2(h0, h1);
    ((uint2*)g_Kl)[idx] = make_uint2(l0, l1);
}
__global__ void prep_v(const float* __restrict__ v) {
    __shared__ float vs[128 * 65];
    const int b = blockIdx.x >> 4, st = blockIdx.x & 15, tid = threadIdx.x;
    const float4* vp = (const float4*)(v + ((size_t)(b * LSEQ + st * 128)) * DH);
#pragma unroll
    for (int it = 0; it < 8; ++it) {
        int fi = it * 256 + tid;
        int s = fi >> 4, d4 = fi & 15;
        float4 x = vp[fi];
        vs[s * 65 + d4 * 4 + 0] = x.x;
        vs[s * 65 + d4 * 4 + 1] = x.y;
        vs[s * 65 + d4 * 4 + 2] = x.z;
        vs[s * 65 + d4 * 4 + 3] = x.w;
    }
    __syncthreads();
#pragma unroll
    for (int it = 0; it < 4; ++it) {
        int fo = it * 256 + tid;
        int d = fo >> 4, cu = fo & 15;
        float vv[8];
#pragma unroll
        for (int j = 0; j < 8; ++j) vv[j] = vs[(cu * 8 + j) * 65 + d];
        uint32_t hw[4], lw[4];
#pragma unroll
        for (int j = 0; j < 4; ++j) split2(vv[2 * j], vv[2 * j + 1], hw[j], lw[j]);
        size_t o = ((size_t)(b * DH + d)) * LSEQ + st * 128 + cu * 8;
        *(uint4*)(g_Vth + o) = make_uint4(hw[0], hw[1], hw[2], hw[3]);
        *(uint4*)(g_Vtl + o) = make_uint4(lw[0], lw[1], lw[2], lw[3]);
    }
}

// ---------------- Fused attention (256 threads, 8 warps) ----------------
// sweep1 smem: QH 0, QL 16K | K bufs 32K, 64K (hi+lo 32K each)
// sweep2 smem: S bufs 0 / 67584 (128 rows x 528B) | V bufs 135168, 167936
// lzs at 200704 (512B)
#define SQH 0
#define SQL 16384
#define SKB(i) (32768 + (i) * 32768)
#define SS(i)  ((i) * 67584)
#define SVB(i) (135168 + (i) * 32768)
#define SLZ 200704
#define SMEM_TOT 201216

__global__ void __launch_bounds__(256, 1)
sdpa_fused(float* __restrict__ attn, float* __restrict__ lattn, float* __restrict__ outp) {
    extern __shared__ char sm[];
    const uint32_t sb = smem_u32(sm);
    const int tid = threadIdx.x, lane = tid & 31, w = tid >> 5;
    const int b = blockIdx.y, qbase = blockIdx.x * 128;

    const int arow = lane & 15, achk = lane >> 4;
    const int brow = ((lane >> 4) << 3) + (lane & 7), bch = (lane >> 3) & 1;
    const int rq = lane >> 2, qd = lane & 3;

    const char* kh_base = (const char*)(g_Kh + (size_t)b * LSEQ * DH);
    const char* kl_base = (const char*)(g_Kl + (size_t)b * LSEQ * DH);
    const char* vh_base = (const char*)(g_Vth + (size_t)b * DH * LSEQ);
    const char* vl_base = (const char*)(g_Vtl + (size_t)b * DH * LSEQ);

#define LOAD_K(buf, t) do {                                                    \
        const char* _sh = kh_base + (size_t)(t) * 16384;                       \
        const char* _sl = kl_base + (size_t)(t) * 16384;                       \
        _Pragma("unroll")                                                      \
        for (int r = 0; r < 4; ++r) {                                          \
            int fo = r * 256 + tid;                                            \
            int row = fo >> 3, cu = fo & 7;                                    \
            uint32_t off = (uint32_t)row * 128 + ((cu ^ (row & 7)) << 4);      \
            cpasync16(sb + (buf) + off, _sh + fo * 16);                        \
            cpasync16(sb + (buf) + 16384 + off, _sl + fo * 16);                \
        }                                                                      \
    } while (0)

#define LOAD_V(buf, t) do {                                                    \
        const char* _sh = vh_base + (size_t)(t) * 256;                         \
        const char* _sl = vl_base + (size_t)(t) * 256;                         \
        _Pragma("unroll")                                                      \
        for (int r = 0; r < 4; ++r) {                                          \
            int fo = r * 256 + tid;                                            \
            int row = fo >> 4, cu = fo & 15;                                   \
            uint32_t off = (uint32_t)row * 256 + ((cu ^ (row & 15)) << 4);     \
            size_t sof = (size_t)row * (LSEQ * 2) + cu * 16;                   \
            cpasync16(sb + (buf) + off, _sh + sof);                            \
            cpasync16(sb + (buf) + 16384 + off, _sl + sof);                    \
        }                                                                      \
    } while (0)

#define LOAD_S(buf, t) do {                                                    \
        const float* _sr = attn + ((size_t)(b * LSEQ + qbase)) * LSEQ + (t) * 128; \
        _Pragma("unroll")                                                      \
        for (int r = 0; r < 16; ++r) {                                         \
            int fo = r * 256 + tid;                                            \
            int row = fo >> 5, cu = fo & 31;                                   \
            cpasync16(sb + SS(buf) + (uint32_t)row * 528 + cu * 16,            \
                      _sr + (size_t)row * LSEQ + cu * 4);                      \
        }                                                                      \
    } while (0)

    // ---- sweep1 prologue: Q tile + K0 ----
    {
        const char* qh = (const char*)(g_Qh + (size_t)(b * LSEQ + qbase) * DH);
        const char* ql = (const char*)(g_Ql + (size_t)(b * LSEQ + qbase) * DH);
#pragma unroll
        for (int r = 0; r < 4; ++r) {
            int fo = r * 256 + tid;
            int row = fo >> 3, cu = fo & 7;
            uint32_t off = (uint32_t)row * 128 + ((cu ^ (row & 7)) << 4);
            cpasync16(sb + SQH + off, qh + fo * 16);
            cpasync16(sb + SQL + off, ql + fo * 16);
        }
        LOAD_K(SKB(0), 0);
        CP_COMMIT();
    }

    uint32_t aQh[4][4], aQl[4][4];
    float mrun[2] = {-INFINITY, -INFINITY}, lrun[2] = {0.f, 0.f};

#define COMPUTE_QK(c, kb) do {                                                 \
        _Pragma("unroll")                                                      \
        for (int nt = 0; nt < 16; ++nt) {                                      \
            c[nt][0] = 0.f; c[nt][1] = 0.f; c[nt][2] = 0.f; c[nt][3] = 0.f;    \
        }                                                                      \
        _Pragma("unroll")                                                      \
        for (int ks = 0; ks < 4; ++ks) {                                       \
            _Pragma("unroll")                                                  \
            for (int p = 0; p < 8; ++p) {                                      \
                int row = p * 16 + brow;                                       \
                uint32_t ad = sb + (kb) + row * 128 +                          \
                              (((ks * 2 + bch) ^ (row & 7)) << 4);             \
                uint32_t bh_[4], bl_[4];                                       \
                ldsm4(bh_, ad);                                                \
                ldsm4(bl_, ad + 16384);                                        \
                mma16816(c[2 * p],     aQh[ks], bh_[0], bh_[1]);               \
                mma16816(c[2 * p + 1], aQh[ks], bh_[2], bh_[3]);               \
                mma16816(c[2 * p],     aQh[ks], bl_[0], bl_[1]);               \
                mma16816(c[2 * p + 1], aQh[ks], bl_[2], bl_[3]);               \
                mma16816(c[2 * p],     aQl[ks], bh_[0], bh_[1]);               \
                mma16816(c[2 * p + 1], aQl[ks], bh_[2], bh_[3]);               \
            }                                                                  \
        }                                                                      \
    } while (0)

    float* aRow = attn + ((size_t)(b * LSEQ + qbase + w * 16 + rq)) * LSEQ + qd * 2;
    float* lRow = lattn + ((size_t)(b * LSEQ + qbase + w * 16 + rq)) * LSEQ + qd * 2;

    // ================= Sweep 1: QK + stats + raw S store =================
    for (int t = 0; t < 16; ++t) {
        CP_WAIT0();
        __syncthreads();
        if (t < 15) {
            LOAD_K(SKB((t + 1) & 1), t + 1);
            CP_COMMIT();
        }
        if (t == 0) {
#pragma unroll
            for (int ks = 0; ks < 4; ++ks) {
                int row = w * 16 + arow;
                uint32_t ad = sb + row * 128 + (((ks * 2 + achk) ^ (row & 7)) << 4);
                ldsm4(aQh[ks], ad);
                ldsm4(aQl[ks], ad + 16384);
            }
        }
        float c[16][4];
        COMPUTE_QK(c, SKB(t & 1));
#pragma unroll
        for (int h = 0; h < 2; ++h) {
            float mx = mrun[h];
#pragma unroll
            for (int nt = 0; nt < 16; ++nt)
                mx = fmaxf(mx, fmaxf(c[nt][2 * h], c[nt][2 * h + 1]));
            float sum = 0.f;
#pragma unroll
            for (int nt = 0; nt < 16; ++nt)
                sum += __expf(c[nt][2 * h] - mx) + __expf(c[nt][2 * h + 1] - mx);
            lrun[h] = lrun[h] * __expf(mrun[h] - mx) + sum;
            mrun[h] = mx;
        }
        float* aT = aRow + t * 128;
#pragma unroll
        for (int nt = 0; nt < 16; ++nt) {
            *(float2*)(aT + nt * 8) = make_float2(c[nt][0], c[nt][1]);
            *(float2*)(aT + 8 * LSEQ + nt * 8) = make_float2(c[nt][2], c[nt][3]);
        }
    }

    // ---- logZ: quad reduce (warp owns full rows) ----
    float* lzs = (float*)(sm + SLZ);
#pragma unroll
    for (int h = 0; h < 2; ++h) {
        float m = mrun[h], l = lrun[h];
#pragma unroll
        for (int o = 1; o <= 2; o <<= 1) {
            float om = __shfl_xor_sync(0xffffffffu, m, o);
            float ol = __shfl_xor_sync(0xffffffffu, l, o);
            float nm = fmaxf(m, om);
            l = l * __expf(m - nm) + ol * __expf(om - nm);
            m = nm;
        }
        if (qd == 0) lzs[w * 16 + rq + 8 * h] = m + logf(l);
    }
    __syncthreads();
    const float lz0 = lzs[w * 16 + rq];
    const float lz1 = lzs[w * 16 + rq + 8];
    __syncthreads();

    // ================= Sweep 2: S stream-back + emit + PV =================
    float o[8][4];
#pragma unroll
    for (int g = 0; g < 8; ++g)
#pragma unroll
        for (int j = 0; j < 4; ++j) o[g][j] = 0.f;

    LOAD_S(0, 0);
    LOAD_V(SVB(0), 0);
    CP_COMMIT();

    for (int t = 0; t < 16; ++t) {
        CP_WAIT0();
        __syncthreads();
        if (t < 15) {
            LOAD_S((t + 1) & 1, t + 1);
            LOAD_V(SVB((t + 1) & 1), t + 1);
            CP_COMMIT();
        }

        const char* sS = sm + SS(t & 1);
        uint32_t aPh[8][4], aPl[8][4];
        float* aT = aRow + t * 128;
        float* lT = lRow + t * 128;
#pragma unroll
        for (int kc = 0; kc < 8; ++kc) {
#pragma unroll
            for (int qq = 0; qq < 2; ++qq) {
                const int nt = 2 * kc + qq;
                float2 s0 = *(const float2*)(sS + (w * 16 + rq) * 0 + rq * 528 + (nt * 8 + qd * 2) * 4 + (w * 16) * 528);
                float2 s1 = *(const float2*)(sS + (rq + 8 + w * 16) * 528 + (nt * 8 + qd * 2) * 4);
                float la0 = s0.x - lz0, la1 = s0.y - lz0;
                float la2 = s1.x - lz1, la3 = s1.y - lz1;
                float p0 = __expf(la0), p1 = __expf(la1);
                float p2 = __expf(la2), p3 = __expf(la3);
                *(float2*)(aT + nt * 8) = make_float2(p0, p1);
                *(float2*)(aT + 8 * LSEQ + nt * 8) = make_float2(p2, p3);
                *(float2*)(lT + nt * 8) = make_float2(la0, la1);
                *(float2*)(lT + 8 * LSEQ + nt * 8) = make_float2(la2, la3);
                uint32_t u0 = __float_as_uint(p0), u1 = __float_as_uint(p1);
                uint32_t u2 = __float_as_uint(p2), u3 = __float_as_uint(p3);
                aPh[kc][qq * 2 + 0] = prmt_hi(u0, u1);
                aPh[kc][qq * 2 + 1] = prmt_hi(u2, u3);
                aPl[kc][qq * 2 + 0] = cvt_bf16x2(p1 - __uint_as_float(u1 & 0xFFFF0000u),
                                                 p0 - __uint_as_float(u0 & 0xFFFF0000u));
                aPl[kc][qq * 2 + 1] = cvt_bf16x2(p3 - __uint_as_float(u3 & 0xFFFF0000u),
                                                 p2 - __uint_as_float(u2 & 0xFFFF0000u));
            }
        }

        const uint32_t vb = sb + SVB(t & 1);
#pragma unroll
        for (int kc = 0; kc < 8; ++kc) {
#pragma unroll
            for (int g2 = 0; g2 < 4; ++g2) {
                int row = g2 * 16 + brow;
                uint32_t ad = vb + row * 256 + (((kc * 2 + bch) ^ (row & 15)) << 4);
                uint32_t vh_[4], vl_[4];
                ldsm4(vh_, ad);
                ldsm4(vl_, ad + 16384);
                mma16816(o[2 * g2],     aPh[kc], vh_[0], vh_[1]);
                mma16816(o[2 * g2 + 1], aPh[kc], vh_[2], vh_[3]);
                mma16816(o[2 * g2],     aPh[kc], vl_[0], vl_[1]);
                mma16816(o[2 * g2 + 1], aPh[kc], vl_[2], vl_[3]);
                mma16816(o[2 * g2],     aPl[kc], vh_[0], vh_[1]);
                mma16816(o[2 * g2 + 1], aPl[kc], vh_[2], vh_[3]);
            }
        }
    }

    // ---- head-folded output ----
    {
        int qr = qbase + w * 16 + rq;
        float* dp = outp + (size_t)qr * (DH * BH) + b * DH + qd * 2;
#pragma unroll
        for (int g = 0; g < 8; ++g) {
            *(float2*)(dp + g * 8) = make_float2(o[g][0], o[g][1]);
            *(float2*)(dp + 8 * (DH * BH) + g * 8) = make_float2(o[g][2], o[g][3]);
        }
    }
}

extern "C" void kernel_launch(void* const* d_in, const int* in_sizes, int n_in,
                              void* d_out, int out_size) {
    const float* q = (const float*)d_in[0];
    const float* k = (const float*)d_in[1];
    const float* v = (const float*)d_in[2];

    float* outp = (float*)d_out;
    float* attn = outp + OUT_ELE;
    float* lattn = attn + ATT_ELE;

    cudaFuncSetAttribute(sdpa_fused, cudaFuncAttributeMaxDynamicSharedMemorySize, SMEM_TOT);

    prep_q<<<2048, 256>>>(q);
    prep_k<<<2048, 256>>>(k);
    prep_v<<<256, 256>>>(v);

    dim3 grid(LSEQ / 128, BH);
    sdpa_fused<<<grid, 256, SMEM_TOT>>>(attn, lattn, outp);
}

// round 10
// speedup vs baseline: 1.0750x; 1.0386x over previous
#include <cuda_runtime.h>
#include <cuda_bf16.h>
#include <cstdint>
#include <math.h>

#define BH 16
#define LSEQ 2048
#define DH 64
#define OUT_ELE (LSEQ * DH * BH)
#define ATT_ELE ((size_t)BH * LSEQ * LSEQ)

__device__ __nv_bfloat16 g_Qh[BH * LSEQ * DH];
__device__ __nv_bfloat16 g_Ql[BH * LSEQ * DH];
__device__ __nv_bfloat16 g_Kh[BH * LSEQ * DH];
__device__ __nv_bfloat16 g_Kl[BH * LSEQ * DH];
__device__ __nv_bfloat16 g_Vth[BH * DH * LSEQ];
__device__ __nv_bfloat16 g_Vtl[BH * DH * LSEQ];

__device__ __forceinline__ uint32_t smem_u32(const void* p) {
    uint32_t a;
    asm("{ .reg .u64 t; cvta.to.shared.u64 t, %1; cvt.u32.u64 %0, t; }" : "=r"(a) : "l"(p));
    return a;
}
__device__ __forceinline__ void ldsm4(uint32_t* r, uint32_t addr) {
    asm volatile("ldmatrix.sync.aligned.m8n8.x4.shared.b16 {%0,%1,%2,%3}, [%4];"
                 : "=r"(r[0]), "=r"(r[1]), "=r"(r[2]), "=r"(r[3]) : "r"(addr));
}
// NOTE: non-volatile on purpose — pure register op, lets the scheduler interleave.
__device__ __forceinline__ void mma16816(float* c, const uint32_t* a, uint32_t b0, uint32_t b1) {
    asm("mma.sync.aligned.m16n8k16.row.col.f32.bf16.bf16.f32 "
        "{%0,%1,%2,%3}, {%4,%5,%6,%7}, {%8,%9}, {%0,%1,%2,%3};"
        : "+f"(c[0]), "+f"(c[1]), "+f"(c[2]), "+f"(c[3])
        : "r"(a[0]), "r"(a[1]), "r"(a[2]), "r"(a[3]), "r"(b0), "r"(b1));
}
__device__ __forceinline__ void split2(float a, float b, uint32_t& hi, uint32_t& lo) {
    __nv_bfloat16 ah = __float2bfloat16(a), bh = __float2bfloat16(b);
    float al = a - __bfloat162float(ah);
    float bl = b - __bfloat162float(bh);
    __nv_bfloat162 H; H.x = ah; H.y = bh;
    __nv_bfloat162 L; L.x = __float2bfloat16(al); L.y = __float2bfloat16(bl);
    hi = *reinterpret_cast<uint32_t*>(&H);
    lo = *reinterpret_cast<uint32_t*>(&L);
}
__device__ __forceinline__ void cpasync16(uint32_t dst, const void* src) {
    asm volatile("cp.async.cg.shared.global [%0], [%1], 16;" :: "r"(dst), "l"(src));
}
#define CP_COMMIT() asm volatile("cp.async.commit_group;" ::: "memory")
#define CP_WAIT0()  asm volatile("cp.async.wait_group 0;" ::: "memory")
__device__ __forceinline__ uint32_t prmt_hi(uint32_t a, uint32_t b) {
    uint32_t d;
    asm("prmt.b32 %0, %1, %2, 0x7632;" : "=r"(d) : "r"(a), "r"(b));
    return d;
}
__device__ __forceinline__ uint32_t cvt_bf16x2(float hi, float lo) {
    uint32_t d;
    asm("cvt.rn.bf16x2.f32 %0, %1, %2;" : "=r"(d) : "f"(hi), "f"(lo));
    return d;
}

// ---------------- Prepass ----------------
__global__ void prep_q(const float* __restrict__ q) {
    int idx = blockIdx.x * 256 + threadIdx.x;
    float4 x = ((const float4*)q)[idx];
    x.x *= 0.125f; x.y *= 0.125f; x.z *= 0.125f; x.w *= 0.125f;
    uint32_t h0, l0, h1, l1;
    split2(x.x, x.y, h0, l0);
    split2(x.z, x.w, h1, l1);
    ((uint2*)g_Qh)[idx] = make_uint2(h0, h1);
    ((uint2*)g_Ql)[idx] = make_uint2(l0, l1);
}
__global__ void prep_k(const float* __restrict__ k) {
    int idx = blockIdx.x * 256 + threadIdx.x;
    float4 x = ((const float4*)k)[idx];
    uint32_t h0, l0, h1, l1;
    split2(x.x, x.y, h0, l0);
    split2(x.z, x.w, h1, l1);
    ((uint2*)g_Kh)[idx] = make_uint2(h0, h1);
    ((uint2*)g_Kl)[idx] = make_uint2(l0, l1);
}
__global__ void prep_v(const float* __restrict__ v) {
    __shared__ float vs[128 * 65];
    const int b = blockIdx.x >> 4, st = blockIdx.x & 15, tid = threadIdx.x;
    const float4* vp = (const float4*)(v + ((size_t)(b * LSEQ + st * 128)) * DH);
#pragma unroll
    for (int it = 0; it < 8; ++it) {
        int fi = it * 256 + tid;
        int s = fi >> 4, d4 = fi & 15;
        float4 x = vp[fi];
        vs[s * 65 + d4 * 4 + 0] = x.x;
        vs[s * 65 + d4 * 4 + 1] = x.y;
        vs[s * 65 + d4 * 4 + 2] = x.z;
        vs[s * 65 + d4 * 4 + 3] = x.w;
    }
    __syncthreads();
#pragma unroll
    for (int it = 0; it < 4; ++it) {
        int fo = it * 256 + tid;
        int d = fo >> 4, cu = fo & 15;
        float vv[8];
#pragma unroll
        for (int j = 0; j < 8; ++j) vv[j] = vs[(cu * 8 + j) * 65 + d];
        uint32_t hw[4], lw[4];
#pragma unroll
        for (int j = 0; j < 4; ++j) split2(vv[2 * j], vv[2 * j + 1], hw[j], lw[j]);
        size_t o = ((size_t)(b * DH + d)) * LSEQ + st * 128 + cu * 8;
        *(uint4*)(g_Vth + o) = make_uint4(hw[0], hw[1], hw[2], hw[3]);
        *(uint4*)(g_Vtl + o) = make_uint4(lw[0], lw[1], lw[2], lw[3]);
    }
}

// ---------------- Fused attention (256 threads, 8 warps) ----------------
#define SQH 0
#define SQL 16384
#define SB0 32768
#define SB1 65536
#define SB2 98304
#define SB3 131072
#define SLZ 163840
#define SMEM_TOT 164352

__global__ void __launch_bounds__(256)
sdpa_fused(float* __restrict__ attn, float* __restrict__ lattn, float* __restrict__ outp) {
    extern __shared__ char sm[];
    const uint32_t sb = smem_u32(sm);
    const int tid = threadIdx.x, lane = tid & 31, w = tid >> 5;
    const int b = blockIdx.y, qbase = blockIdx.x * 128;

    const int arow = lane & 15, achk = lane >> 4;
    const int brow = ((lane >> 4) << 3) + (lane & 7), bch = (lane >> 3) & 1;
    const int rq = lane >> 2, qd = lane & 3;

    const char* kh_base = (const char*)(g_Kh + (size_t)b * LSEQ * DH);
    const char* kl_base = (const char*)(g_Kl + (size_t)b * LSEQ * DH);
    const char* vh_base = (const char*)(g_Vth + (size_t)b * DH * LSEQ);
    const char* vl_base = (const char*)(g_Vtl + (size_t)b * DH * LSEQ);

#define LOAD_K(buf, t) do {                                                    \
        const char* _sh = kh_base + (size_t)(t) * 16384;                       \
        const char* _sl = kl_base + (size_t)(t) * 16384;                       \
        _Pragma("unroll")                                                      \
        for (int r = 0; r < 4; ++r) {                                          \
            int fo = r * 256 + tid;                                            \
            int row = fo >> 3, cu = fo & 7;                                    \
            uint32_t off = (uint32_t)row * 128 + ((cu ^ (row & 7)) << 4);      \
            cpasync16(sb + (buf) + off, _sh + fo * 16);                        \
            cpasync16(sb + (buf) + 16384 + off, _sl + fo * 16);                \
        }                                                                      \
    } while (0)

#define LOAD_V(buf, t) do {                                                    \
        const char* _sh = vh_base + (size_t)(t) * 256;                         \
        const char* _sl = vl_base + (size_t)(t) * 256;                         \
        _Pragma("unroll")                                                      \
        for (int r = 0; r < 4; ++r) {                                          \
            int fo = r * 256 + tid;                                            \
            int row = fo >> 4, cu = fo & 15;                                   \
            uint32_t off = (uint32_t)row * 256 + ((cu ^ (row & 15)) << 4);     \
            size_t sof = (size_t)row * (LSEQ * 2) + cu * 16;                   \
            cpasync16(sb + (buf) + off, _sh + sof);                            \
            cpasync16(sb + (buf) + 16384 + off, _sl + sof);                    \
        }                                                                      \
    } while (0)

    // ---- prologue: Q tile + K0 ----
    {
        const char* qh = (const char*)(g_Qh + (size_t)(b * LSEQ + qbase) * DH);
        const char* ql = (const char*)(g_Ql + (size_t)(b * LSEQ + qbase) * DH);
#pragma unroll
        for (int r = 0; r < 4; ++r) {
            int fo = r * 256 + tid;
            int row = fo >> 3, cu = fo & 7;
            uint32_t off = (uint32_t)row * 128 + ((cu ^ (row & 7)) << 4);
            cpasync16(sb + SQH + off, qh + fo * 16);
            cpasync16(sb + SQL + off, ql + fo * 16);
        }
        LOAD_K(SB0, 0);
        CP_COMMIT();
    }

    uint32_t aQh[4][4], aQl[4][4];
    float mrun[2] = {-INFINITY, -INFINITY}, lrun[2] = {0.f, 0.f};

    // QK with distance-4 accumulator pairing: process p in pairs, cycle 4 accs.
#define COMPUTE_QK(c, kb) do {                                                 \
        _Pragma("unroll")                                                      \
        for (int nt = 0; nt < 16; ++nt) {                                      \
            c[nt][0] = 0.f; c[nt][1] = 0.f; c[nt][2] = 0.f; c[nt][3] = 0.f;    \
        }                                                                      \
        _Pragma("unroll")                                                      \
        for (int ks = 0; ks < 4; ++ks) {                                       \
            _Pragma("unroll")                                                  \
            for (int pp = 0; pp < 4; ++pp) {                                   \
                int row0 = (2 * pp) * 16 + brow;                               \
                int row1 = (2 * pp + 1) * 16 + brow;                           \
                uint32_t ad0 = sb + (kb) + row0 * 128 +                        \
                               (((ks * 2 + bch) ^ (row0 & 7)) << 4);           \
                uint32_t ad1 = sb + (kb) + row1 * 128 +                        \
                               (((ks * 2 + bch) ^ (row1 & 7)) << 4);           \
                uint32_t bh0[4], bh1[4], bl0[4], bl1[4];                       \
                ldsm4(bh0, ad0);                                               \
                ldsm4(bh1, ad1);                                               \
                ldsm4(bl0, ad0 + 16384);                                       \
                ldsm4(bl1, ad1 + 16384);                                       \
                mma16816(c[4*pp+0], aQh[ks], bh0[0], bh0[1]);                  \
                mma16816(c[4*pp+1], aQh[ks], bh0[2], bh0[3]);                  \
                mma16816(c[4*pp+2], aQh[ks], bh1[0], bh1[1]);                  \
                mma16816(c[4*pp+3], aQh[ks], bh1[2], bh1[3]);                  \
                mma16816(c[4*pp+0], aQh[ks], bl0[0], bl0[1]);                  \
                mma16816(c[4*pp+1], aQh[ks], bl0[2], bl0[3]);                  \
                mma16816(c[4*pp+2], aQh[ks], bl1[0], bl1[1]);                  \
                mma16816(c[4*pp+3], aQh[ks], bl1[2], bl1[3]);                  \
                mma16816(c[4*pp+0], aQl[ks], bh0[0], bh0[1]);                  \
                mma16816(c[4*pp+1], aQl[ks], bh0[2], bh0[3]);                  \
                mma16816(c[4*pp+2], aQl[ks], bh1[0], bh1[1]);                  \
                mma16816(c[4*pp+3], aQl[ks], bh1[2], bh1[3]);                  \
            }                                                                  \
        }                                                                      \
    } while (0)

    // ================= Sweep 1: stats =================
    for (int t = 0; t < 16; ++t) {
        CP_WAIT0();
        __syncthreads();
        if (t < 15) {
            LOAD_K(((t + 1) & 1) ? SB1 : SB0, t + 1);
            CP_COMMIT();
        }
        if (t == 0) {
#pragma unroll
            for (int ks = 0; ks < 4; ++ks) {
                int row = w * 16 + arow;
                uint32_t ad = sb + row * 128 + (((ks * 2 + achk) ^ (row & 7)) << 4);
                ldsm4(aQh[ks], ad);
                ldsm4(aQl[ks], ad + 16384);
            }
        }
        float c[16][4];
        COMPUTE_QK(c, ((t & 1) ? SB1 : SB0));
#pragma unroll
        for (int h = 0; h < 2; ++h) {
            float mx = mrun[h];
#pragma unroll
            for (int nt = 0; nt < 16; ++nt)
                mx = fmaxf(mx, fmaxf(c[nt][2 * h], c[nt][2 * h + 1]));
            float sum = 0.f;
#pragma unroll
            for (int nt = 0; nt < 16; ++nt)
                sum += __expf(c[nt][2 * h] - mx) + __expf(c[nt][2 * h + 1] - mx);
            lrun[h] = lrun[h] * __expf(mrun[h] - mx) + sum;
            mrun[h] = mx;
        }
    }

    // ---- logZ: quad reduce (each warp owns full 16 rows) ----
    float* lzs = (float*)(sm + SLZ);
#pragma unroll
    for (int h = 0; h < 2; ++h) {
        float m = mrun[h], l = lrun[h];
#pragma unroll
        for (int o = 1; o <= 2; o <<= 1) {
            float om = __shfl_xor_sync(0xffffffffu, m, o);
            float ol = __shfl_xor_sync(0xffffffffu, l, o);
            float nm = fmaxf(m, om);
            l = l * __expf(m - nm) + ol * __expf(om - nm);
            m = nm;
        }
        if (qd == 0) lzs[w * 16 + rq + 8 * h] = m + logf(l);
    }
    __syncwarp();
    const float lz0 = lzs[w * 16 + rq];
    const float lz1 = lzs[w * 16 + rq + 8];

    // ================= Sweep 2: recompute QK, emit, PV =================
    float o[8][4];
#pragma unroll
    for (int g = 0; g < 8; ++g)
#pragma unroll
        for (int j = 0; j < 4; ++j) o[g][j] = 0.f;

    __syncthreads();
    LOAD_K(SB0, 0);
    LOAD_V(SB2, 0);
    CP_COMMIT();

    float* aRow = attn + ((size_t)(b * LSEQ + qbase + w * 16 + rq)) * LSEQ + qd * 2;
    float* lRow = lattn + ((size_t)(b * LSEQ + qbase + w * 16 + rq)) * LSEQ + qd * 2;

    for (int t = 0; t < 16; ++t) {
        CP_WAIT0();
        __syncthreads();
        if (t < 15) {
            LOAD_K(((t + 1) & 1) ? SB1 : SB0, t + 1);
            LOAD_V(((t + 1) & 1) ? SB3 : SB2, t + 1);
            CP_COMMIT();
        }

        float c[16][4];
        COMPUTE_QK(c, ((t & 1) ? SB1 : SB0));

        // convert: attn/lattn stores + register-resident P fragments
        uint32_t aPh[8][4], aPl[8][4];
        float* aT = aRow + t * 128;
        float* lT = lRow + t * 128;
#pragma unroll
        for (int kc = 0; kc < 8; ++kc) {
#pragma unroll
            for (int qq = 0; qq < 2; ++qq) {
                const int nt = 2 * kc + qq;
                float la0 = c[nt][0] - lz0, la1 = c[nt][1] - lz0;
                float la2 = c[nt][2] - lz1, la3 = c[nt][3] - lz1;
                float p0 = __expf(la0), p1 = __expf(la1);
                float p2 = __expf(la2), p3 = __expf(la3);
                *(float2*)(aT + nt * 8) = make_float2(p0, p1);
                *(float2*)(aT + 8 * LSEQ + nt * 8) = make_float2(p2, p3);
                *(float2*)(lT + nt * 8) = make_float2(la0, la1);
                *(float2*)(lT + 8 * LSEQ + nt * 8) = make_float2(la2, la3);
                uint32_t u0 = __float_as_uint(p0), u1 = __float_as_uint(p1);
                uint32_t u2 = __float_as_uint(p2), u3 = __float_as_uint(p3);
                aPh[kc][qq * 2 + 0] = prmt_hi(u0, u1);
                aPh[kc][qq * 2 + 1] = prmt_hi(u2, u3);
                aPl[kc][qq * 2 + 0] = cvt_bf16x2(p1 - __uint_as_float(u1 & 0xFFFF0000u),
                                                 p0 - __uint_as_float(u0 & 0xFFFF0000u));
                aPl[kc][qq * 2 + 1] = cvt_bf16x2(p3 - __uint_as_float(u3 & 0xFFFF0000u),
                                                 p2 - __uint_as_float(u2 & 0xFFFF0000u));
            }
        }

        // PV with distance-4 pairing: O += Ph*Vh + Ph*Vl + Pl*Vh
        const uint32_t vb = sb + ((t & 1) ? SB3 : SB2);
#pragma unroll
        for (int kc = 0; kc < 8; ++kc) {
#pragma unroll
            for (int gg = 0; gg < 2; ++gg) {
                int row0 = (2 * gg) * 16 + brow;
                int row1 = (2 * gg + 1) * 16 + brow;
                uint32_t ad0 = vb + row0 * 256 + (((kc * 2 + bch) ^ (row0 & 15)) << 4);
                uint32_t ad1 = vb + row1 * 256 + (((kc * 2 + bch) ^ (row1 & 15)) << 4);
                uint32_t vh0[4], vh1[4], vl0[4], vl1[4];
                ldsm4(vh0, ad0);
                ldsm4(vh1, ad1);
                ldsm4(vl0, ad0 + 16384);
                ldsm4(vl1, ad1 + 16384);
                mma16816(o[4*gg+0], aPh[kc], vh0[0], vh0[1]);
                mma16816(o[4*gg+1], aPh[kc], vh0[2], vh0[3]);
                mma16816(o[4*gg+2], aPh[kc], vh1[0], vh1[1]);
                mma16816(o[4*gg+3], aPh[kc], vh1[2], vh1[3]);
                mma16816(o[4*gg+0], aPh[kc], vl0[0], vl0[1]);
                mma16816(o[4*gg+1], aPh[kc], vl0[2], vl0[3]);
                mma16816(o[4*gg+2], aPh[kc], vl1[0], vl1[1]);
                mma16816(o[4*gg+3], aPh[kc], vl1[2], vl1[3]);
                mma16816(o[4*gg+0], aPl[kc], vh0[0], vh0[1]);
                mma16816(o[4*gg+1], aPl[kc], vh0[2], vh0[3]);
                mma16816(o[4*gg+2], aPl[kc], vh1[0], vh1[1]);
                mma16816(o[4*gg+3], aPl[kc], vh1[2], vh1[3]);
            }
        }
    }

    // ---- head-folded output ----
    {
        int qr = qbase + w * 16 + rq;
        float* dp = outp + (size_t)qr * (DH * BH) + b * DH + qd * 2;
#pragma unroll
        for (int g = 0; g < 8; ++g) {
            *(float2*)(dp + g * 8) = make_float2(o[g][0], o[g][1]);
            *(float2*)(dp + 8 * (DH * BH) + g * 8) = make_float2(o[g][2], o[g][3]);
        }
    }
}

extern "C" void kernel_launch(void* const* d_in, const int* in_sizes, int n_in,
                              void* d_out, int out_size) {
    const float* q = (const float*)d_in[0];
    const float* k = (const float*)d_in[1];
    const float* v = (const float*)d_in[2];

    float* outp = (float*)d_out;
    float* attn = outp + OUT_ELE;
    float* lattn = attn + ATT_ELE;

    cudaFuncSetAttribute(sdpa_fused, cudaFuncAttributeMaxDynamicSharedMemorySize, SMEM_TOT);

    prep_q<<<2048, 256>>>(q);
    prep_k<<<2048, 256>>>(k);
    prep_v<<<256, 256>>>(v);

    dim3 grid(LSEQ / 128, BH);
    sdpa_fused<<<grid, 256, SMEM_TOT>>>(attn, lattn, outp);
}

// round 12
// speedup vs baseline: 1.1423x; 1.0626x over previous
#include <cuda_runtime.h>
#include <cuda_bf16.h>
#include <cstdint>
#include <math.h>

#define BH 16
#define LSEQ 2048
#define DH 64
#define OUT_ELE (LSEQ * DH * BH)
#define ATT_ELE ((size_t)BH * LSEQ * LSEQ)

__device__ __nv_bfloat16 g_Qh[BH * LSEQ * DH];
__device__ __nv_bfloat16 g_Ql[BH * LSEQ * DH];
__device__ __nv_bfloat16 g_Kh[BH * LSEQ * DH];
__device__ __nv_bfloat16 g_Kl[BH * LSEQ * DH];
__device__ __nv_bfloat16 g_Vth[BH * DH * LSEQ];
__device__ __nv_bfloat16 g_Vtl[BH * DH * LSEQ];

__device__ __forceinline__ uint32_t smem_u32(const void* p) {
    uint32_t a;
    asm("{ .reg .u64 t; cvta.to.shared.u64 t, %1; cvt.u32.u64 %0, t; }" : "=r"(a) : "l"(p));
    return a;
}
__device__ __forceinline__ void ldsm4(uint32_t* r, uint32_t addr) {
    asm volatile("ldmatrix.sync.aligned.m8n8.x4.shared.b16 {%0,%1,%2,%3}, [%4];"
                 : "=r"(r[0]), "=r"(r[1]), "=r"(r[2]), "=r"(r[3]) : "r"(addr));
}
__device__ __forceinline__ void mma16816(float* c, const uint32_t* a, uint32_t b0, uint32_t b1) {
    asm("mma.sync.aligned.m16n8k16.row.col.f32.bf16.bf16.f32 "
        "{%0,%1,%2,%3}, {%4,%5,%6,%7}, {%8,%9}, {%0,%1,%2,%3};"
        : "+f"(c[0]), "+f"(c[1]), "+f"(c[2]), "+f"(c[3])
        : "r"(a[0]), "r"(a[1]), "r"(a[2]), "r"(a[3]), "r"(b0), "r"(b1));
}
__device__ __forceinline__ void split2(float a, float b, uint32_t& hi, uint32_t& lo) {
    __nv_bfloat16 ah = __float2bfloat16(a), bh = __float2bfloat16(b);
    float al = a - __bfloat162float(ah);
    float bl = b - __bfloat162float(bh);
    __nv_bfloat162 H; H.x = ah; H.y = bh;
    __nv_bfloat162 L; L.x = __float2bfloat16(al); L.y = __float2bfloat16(bl);
    hi = *reinterpret_cast<uint32_t*>(&H);
    lo = *reinterpret_cast<uint32_t*>(&L);
}
__device__ __forceinline__ void cpasync16(uint32_t dst, const void* src) {
    asm volatile("cp.async.cg.shared.global [%0], [%1], 16;" :: "r"(dst), "l"(src));
}
#define CP_COMMIT() asm volatile("cp.async.commit_group;" ::: "memory")
#define CP_WAIT0()  asm volatile("cp.async.wait_group 0;" ::: "memory")
__device__ __forceinline__ uint32_t prmt_hi(uint32_t a, uint32_t b) {
    uint32_t d;
    asm("prmt.b32 %0, %1, %2, 0x7632;" : "=r"(d) : "r"(a), "r"(b));
    return d;
}
__device__ __forceinline__ uint32_t cvt_bf16x2(float hi, float lo) {
    uint32_t d;
    asm("cvt.rn.bf16x2.f32 %0, %1, %2;" : "=r"(d) : "f"(hi), "f"(lo));
    return d;
}

// ---------------- Prepass ----------------
__global__ void prep_q(const float* __restrict__ q) {
    int idx = blockIdx.x * 256 + threadIdx.x;
    float4 x = ((const float4*)q)[idx];
    x.x *= 0.125f; x.y *= 0.125f; x.z *= 0.125f; x.w *= 0.125f;
    uint32_t h0, l0, h1, l1;
    split2(x.x, x.y, h0, l0);
    split2(x.z, x.w, h1, l1);
    ((uint2*)g_Qh)[idx] = make_uint2(h0, h1);
    ((uint2*)g_Ql)[idx] = make_uint2(l0, l1);
}
__global__ void prep_k(const float* __restrict__ k) {
    int idx = blockIdx.x * 256 + threadIdx.x;
    float4 x = ((const float4*)k)[idx];
    uint32_t h0, l0, h1, l1;
    split2(x.x, x.y, h0, l0);
    split2(x.z, x.w, h1, l1);
    ((uint2*)g_Kh)[idx] = make_uint2(h0, h1);
    ((uint2*)g_Kl)[idx] = make_uint2(l0, l1);
}
__global__ void prep_v(const float* __restrict__ v) {
    __shared__ float vs[128 * 65];
    const int b = blockIdx.x >> 4, st = blockIdx.x & 15, tid = threadIdx.x;
    const float4* vp = (const float4*)(v + ((size_t)(b * LSEQ + st * 128)) * DH);
#pragma unroll
    for (int it = 0; it < 8; ++it) {
        int fi = it * 256 + tid;
        int s = fi >> 4, d4 = fi & 15;
        float4 x = vp[fi];
        vs[s * 65 + d4 * 4 + 0] = x.x;
        vs[s * 65 + d4 * 4 + 1] = x.y;
        vs[s * 65 + d4 * 4 + 2] = x.z;
        vs[s * 65 + d4 * 4 + 3] = x.w;
    }
    __syncthreads();
#pragma unroll
    for (int it = 0; it < 4; ++it) {
        int fo = it * 256 + tid;
        int d = fo >> 4, cu = fo & 15;
        float vv[8];
#pragma unroll
        for (int j = 0; j < 8; ++j) vv[j] = vs[(cu * 8 + j) * 65 + d];
        uint32_t hw[4], lw[4];
#pragma unroll
        for (int j = 0; j < 4; ++j) split2(vv[2 * j], vv[2 * j + 1], hw[j], lw[j]);
        size_t o = ((size_t)(b * DH + d)) * LSEQ + st * 128 + cu * 8;
        *(uint4*)(g_Vth + o) = make_uint4(hw[0], hw[1], hw[2], hw[3]);
        *(uint4*)(g_Vtl + o) = make_uint4(lw[0], lw[1], lw[2], lw[3]);
    }
}

// ---------------- Fused attention (128 threads, 4 warps, 64 q-rows/CTA) ----------------
// smem: Q hi 0..8K, Q lo 8K..16K
//       K bufs: SK0 16K..32K, SK1 32K..48K   (each = hi 8K + lo 8K; 64 seq x 64 d)
//       V bufs: SV0 48K..64K, SV1 64K..80K   (each = hi 8K + lo 8K; 64 d x 64 seq)
//       lzs 80K (512B). Total 82432 -> 2 CTAs/SM.
#define SQH 0
#define SQL 8192
#define SK(i) (16384 + (i) * 16384)
#define SV(i) (49152 + (i) * 16384)
#define SLZ 81920
#define SMEM_TOT 82432

__global__ void __launch_bounds__(128, 2)
sdpa_fused(float* __restrict__ attn, float* __restrict__ lattn, float* __restrict__ outp) {
    extern __shared__ char sm[];
    const uint32_t sb = smem_u32(sm);
    const int tid = threadIdx.x, lane = tid & 31, w = tid >> 5;   // w in 0..3
    const int b = blockIdx.y, qbase = blockIdx.x * 64;

    const int arow = lane & 15, achk = lane >> 4;
    const int brow = ((lane >> 4) << 3) + (lane & 7), bch = (lane >> 3) & 1;
    const int rq = lane >> 2, qd = lane & 3;

    const char* kh_base = (const char*)(g_Kh + (size_t)b * LSEQ * DH);
    const char* kl_base = (const char*)(g_Kl + (size_t)b * LSEQ * DH);
    const char* vh_base = (const char*)(g_Vth + (size_t)b * DH * LSEQ);
    const char* vl_base = (const char*)(g_Vtl + (size_t)b * DH * LSEQ);

    // K chunk u: seq rows u*64..u*64+63, all 64 d. 8KB hi + 8KB lo.
#define LOAD_K(buf, u) do {                                                    \
        const char* _sh = kh_base + (size_t)(u) * 8192;                        \
        const char* _sl = kl_base + (size_t)(u) * 8192;                        \
        _Pragma("unroll")                                                      \
        for (int r = 0; r < 4; ++r) {                                          \
            int fo = r * 128 + tid;                                            \
            int row = fo >> 3, cu = fo & 7;                                    \
            uint32_t off = (uint32_t)row * 128 + ((cu ^ (row & 7)) << 4);      \
            cpasync16(sb + (buf) + off, _sh + fo * 16);                        \
            cpasync16(sb + (buf) + 8192 + off, _sl + fo * 16);                 \
        }                                                                      \
    } while (0)

    // V chunk u: d rows 0..63, seq cols u*64..u*64+63 (128B per row-chunk).
#define LOAD_V(buf, u) do {                                                    \
        _Pragma("unroll")                                                      \
        for (int r = 0; r < 4; ++r) {                                          \
            int fo = r * 128 + tid;                                            \
            int row = fo >> 3, cu = fo & 7;                                    \
            uint32_t off = (uint32_t)row * 128 + ((cu ^ (row & 7)) << 4);      \
            size_t sof = (size_t)row * (LSEQ * 2) + (size_t)(u) * 128 + cu * 16; \
            cpasync16(sb + (buf) + off, vh_base + sof);                        \
            cpasync16(sb + (buf) + 8192 + off, vl_base + sof);                 \
        }                                                                      \
    } while (0)

    // ---- prologue: Q tile (64x64, hi+lo) + K chunk 0 ----
    {
        const char* qh = (const char*)(g_Qh + (size_t)(b * LSEQ + qbase) * DH);
        const char* ql = (const char*)(g_Ql + (size_t)(b * LSEQ + qbase) * DH);
#pragma unroll
        for (int r = 0; r < 4; ++r) {
            int fo = r * 128 + tid;
            int row = fo >> 3, cu = fo & 7;
            uint32_t off = (uint32_t)row * 128 + ((cu ^ (row & 7)) << 4);
            cpasync16(sb + SQH + off, qh + fo * 16);
            cpasync16(sb + SQL + off, ql + fo * 16);
        }
        LOAD_K(SK(0), 0);
        CP_COMMIT();
    }

    uint32_t aQh[4][4], aQl[4][4];
    float mrun[2] = {-INFINITY, -INFINITY}, lrun[2] = {0.f, 0.f};

    // QK over one 64-col chunk: c[8][4], distance-4 accumulator pairing.
#define COMPUTE_QK(c, kb) do {                                                 \
        _Pragma("unroll")                                                      \
        for (int nt = 0; nt < 8; ++nt) {                                       \
            c[nt][0] = 0.f; c[nt][1] = 0.f; c[nt][2] = 0.f; c[nt][3] = 0.f;    \
        }                                                                      \
        _Pragma("unroll")                                                      \
        for (int ks = 0; ks < 4; ++ks) {                                       \
            _Pragma("unroll")                                                  \
            for (int pp = 0; pp < 2; ++pp) {                                   \
                int row0 = pp * 32 + brow;                                     \
                int row1 = row0 + 16;                                          \
                uint32_t ad0 = sb + (kb) + row0 * 128 +                        \
                               (((ks * 2 + bch) ^ (row0 & 7)) << 4);           \
                uint32_t ad1 = sb + (kb) + row1 * 128 +                        \
                               (((ks * 2 + bch) ^ (row1 & 7)) << 4);           \
                uint32_t bh0[4], bh1[4], bl0[4], bl1[4];                       \
                ldsm4(bh0, ad0);                                               \
                ldsm4(bh1, ad1);                                               \
                ldsm4(bl0, ad0 + 8192);                                        \
                ldsm4(bl1, ad1 + 8192);                                        \
                mma16816(c[4*pp+0], aQh[ks], bh0[0], bh0[1]);                  \
                mma16816(c[4*pp+1], aQh[ks], bh0[2], bh0[3]);                  \
                mma16816(c[4*pp+2], aQh[ks], bh1[0], bh1[1]);                  \
                mma16816(c[4*pp+3], aQh[ks], bh1[2], bh1[3]);                  \
                mma16816(c[4*pp+0], aQh[ks], bl0[0], bl0[1]);                  \
                mma16816(c[4*pp+1], aQh[ks], bl0[2], bl0[3]);                  \
                mma16816(c[4*pp+2], aQh[ks], bl1[0], bl1[1]);                  \
                mma16816(c[4*pp+3], aQh[ks], bl1[2], bl1[3]);                  \
                mma16816(c[4*pp+0], aQl[ks], bh0[0], bh0[1]);                  \
                mma16816(c[4*pp+1], aQl[ks], bh0[2], bh0[3]);                  \
                mma16816(c[4*pp+2], aQl[ks], bh1[0], bh1[1]);                  \
                mma16816(c[4*pp+3], aQl[ks], bh1[2], bh1[3]);                  \
            }                                                                  \
        }                                                                      \
    } while (0)

    // ================= Sweep 1: stats (32 chunks of 64 kv) =================
    for (int u = 0; u < 32; ++u) {
        CP_WAIT0();
        __syncthreads();
        if (u < 31) {
            LOAD_K(SK((u + 1) & 1), u + 1);
            CP_COMMIT();
        }
        if (u == 0) {
#pragma unroll
            for (int ks = 0; ks < 4; ++ks) {
                int row = w * 16 + arow;
                uint32_t ad = sb + SQH + row * 128 + (((ks * 2 + achk) ^ (row & 7)) << 4);
                ldsm4(aQh[ks], ad);
                ldsm4(aQl[ks], ad + 8192);
            }
        }
        float c[8][4];
        COMPUTE_QK(c, SK(u & 1));
#pragma unroll
        for (int h = 0; h < 2; ++h) {
            float mx = mrun[h];
#pragma unroll
            for (int nt = 0; nt < 8; ++nt)
                mx = fmaxf(mx, fmaxf(c[nt][2 * h], c[nt][2 * h + 1]));
            float sum = 0.f;
#pragma unroll
            for (int nt = 0; nt < 8; ++nt)
                sum += __expf(c[nt][2 * h] - mx) + __expf(c[nt][2 * h + 1] - mx);
            lrun[h] = lrun[h] * __expf(mrun[h] - mx) + sum;
            mrun[h] = mx;
        }
    }

    // ---- logZ: quad reduce, broadcast via dedicated lzs region ----
    float* lzs = (float*)(sm + SLZ);
#pragma unroll
    for (int h = 0; h < 2; ++h) {
        float m = mrun[h], l = lrun[h];
#pragma unroll
        for (int o = 1; o <= 2; o <<= 1) {
            float om = __shfl_xor_sync(0xffffffffu, m, o);
            float ol = __shfl_xor_sync(0xffffffffu, l, o);
            float nm = fmaxf(m, om);
            l = l * __expf(m - nm) + ol * __expf(om - nm);
            m = nm;
        }
        if (qd == 0) lzs[w * 16 + rq + 8 * h] = m + logf(l);
    }
    __syncwarp();
    const float lz0 = lzs[w * 16 + rq];
    const float lz1 = lzs[w * 16 + rq + 8];

    // ================= Sweep 2: recompute QK, emit, PV =================
    float o[8][4];
#pragma unroll
    for (int g = 0; g < 8; ++g)
#pragma unroll
        for (int j = 0; j < 4; ++j) o[g][j] = 0.f;

    __syncthreads();
    LOAD_K(SK(0), 0);
    LOAD_V(SV(0), 0);
    CP_COMMIT();

    float* aRow = attn + ((size_t)(b * LSEQ + qbase + w * 16 + rq)) * LSEQ + qd * 2;
    float* lRow = lattn + ((size_t)(b * LSEQ + qbase + w * 16 + rq)) * LSEQ + qd * 2;

    for (int u = 0; u < 32; ++u) {
        CP_WAIT0();
        __syncthreads();
        if (u < 31) {
            LOAD_K(SK((u + 1) & 1), u + 1);
            LOAD_V(SV((u + 1) & 1), u + 1);
            CP_COMMIT();
        }

        float c[8][4];
        COMPUTE_QK(c, SK(u & 1));

        // convert: attn/lattn stores + register-resident P fragments (64 cols)
        uint32_t aPh[4][4], aPl[4][4];
        float* aT = aRow + u * 64;
        float* lT = lRow + u * 64;
#pragma unroll
        for (int kc = 0; kc < 4; ++kc) {
#pragma unroll
            for (int qq = 0; qq < 2; ++qq) {
                const int nt = 2 * kc + qq;
                float la0 = c[nt][0] - lz0, la1 = c[nt][1] - lz0;
                float la2 = c[nt][2] - lz1, la3 = c[nt][3] - lz1;
                float p0 = __expf(la0), p1 = __expf(la1);
                float p2 = __expf(la2), p3 = __expf(la3);
                *(float2*)(aT + nt * 8) = make_float2(p0, p1);
                *(float2*)(aT + 8 * LSEQ + nt * 8) = make_float2(p2, p3);
                *(float2*)(lT + nt * 8) = make_float2(la0, la1);
                *(float2*)(lT + 8 * LSEQ + nt * 8) = make_float2(la2, la3);
                uint32_t u0 = __float_as_uint(p0), u1 = __float_as_uint(p1);
                uint32_t u2 = __float_as_uint(p2), u3 = __float_as_uint(p3);
                aPh[kc][qq * 2 + 0] = prmt_hi(u0, u1);
                aPh[kc][qq * 2 + 1] = prmt_hi(u2, u3);
                aPl[kc][qq * 2 + 0] = cvt_bf16x2(p1 - __uint_as_float(u1 & 0xFFFF0000u),
                                                 p0 - __uint_as_float(u0 & 0xFFFF0000u));
                aPl[kc][qq * 2 + 1] = cvt_bf16x2(p3 - __uint_as_float(u3 & 0xFFFF0000u),
                                                 p2 - __uint_as_float(u2 & 0xFFFF0000u));
            }
        }

        // PV over this 64-kv chunk: O += Ph*Vh + Ph*Vl + Pl*Vh
        const uint32_t vb = sb + SV(u & 1);
#pragma unroll
        for (int kc = 0; kc < 4; ++kc) {
#pragma unroll
            for (int gg = 0; gg < 2; ++gg) {
                int row0 = gg * 32 + brow;     // d rows
                int row1 = row0 + 16;
                uint32_t ad0 = vb + row0 * 128 + (((kc * 2 + bch) ^ (row0 & 7)) << 4);
                uint32_t ad1 = vb + row1 * 128 + (((kc * 2 + bch) ^ (row1 & 7)) << 4);
                uint32_t vh0[4], vh1[4], vl0[4], vl1[4];
                ldsm4(vh0, ad0);
                ldsm4(vh1, ad1);
                ldsm4(vl0, ad0 + 8192);
                ldsm4(vl1, ad1 + 8192);
                mma16816(o[4*gg+0], aPh[kc], vh0[0], vh0[1]);
                mma16816(o[4*gg+1], aPh[kc], vh0[2], vh0[3]);
                mma16816(o[4*gg+2], aPh[kc], vh1[0], vh1[1]);
                mma16816(o[4*gg+3], aPh[kc], vh1[2], vh1[3]);
                mma16816(o[4*gg+0], aPh[kc], vl0[0], vl0[1]);
                mma16816(o[4*gg+1], aPh[kc], vl0[2], vl0[3]);
                mma16816(o[4*gg+2], aPh[kc], vl1[0], vl1[1]);
                mma16816(o[4*gg+3], aPh[kc], vl1[2], vl1[3]);
                mma16816(o[4*gg+0], aPl[kc], vh0[0], vh0[1]);
                mma16816(o[4*gg+1], aPl[kc], vh0[2], vh0[3]);
                mma16816(o[4*gg+2], aPl[kc], vh1[0], vh1[1]);
                mma16816(o[4*gg+3], aPl[kc], vh1[2], vh1[3]);
            }
        }
    }

    // ---- head-folded output (warp owns full rows; no cross-warp reduce) ----
    {
        int qr = qbase + w * 16 + rq;
        float* dp = outp + (size_t)qr * (DH * BH) + b * DH + qd * 2;
#pragma unroll
        for (int g = 0; g < 8; ++g) {
            *(float2*)(dp + g * 8) = make_float2(o[g][0], o[g][1]);
            *(float2*)(dp + 8 * (DH * BH) + g * 8) = make_float2(o[g][2], o[g][3]);
        }
    }
}

extern "C" void kernel_launch(void* const* d_in, const int* in_sizes, int n_in,
                              void* d_out, int out_size) {
    const float* q = (const float*)d_in[0];
    const float* k = (const float*)d_in[1];
    const float* v = (const float*)d_in[2];

    float* outp = (float*)d_out;
    float* attn = outp + OUT_ELE;
    float* lattn = attn + ATT_ELE;

    cudaFuncSetAttribute(sdpa_fused, cudaFuncAttributeMaxDynamicSharedMemorySize, SMEM_TOT);

    prep_q<<<2048, 256>>>(q);
    prep_k<<<2048, 256>>>(k);
    prep_v<<<256, 256>>>(v);

    dim3 grid(LSEQ / 64, BH);
    sdpa_fused<<<grid, 128, SMEM_TOT>>>(attn, lattn, outp);
}

// round 13
// speedup vs baseline: 1.3589x; 1.1896x over previous
#include <cuda_runtime.h>
#include <cuda_bf16.h>
#include <cstdint>
#include <math.h>

#define BH 16
#define LSEQ 2048
#define DH 64
#define OUT_ELE (LSEQ * DH * BH)
#define ATT_ELE ((size_t)BH * LSEQ * LSEQ)

__device__ __nv_bfloat16 g_Qh[BH * LSEQ * DH];
__device__ __nv_bfloat16 g_Ql[BH * LSEQ * DH];
__device__ __nv_bfloat16 g_Kh[BH * LSEQ * DH];
__device__ __nv_bfloat16 g_Kl[BH * LSEQ * DH];
__device__ __nv_bfloat16 g_Vth[BH * DH * LSEQ];
__device__ __nv_bfloat16 g_Vtl[BH * DH * LSEQ];

__device__ __forceinline__ uint32_t smem_u32(const void* p) {
    uint32_t a;
    asm("{ .reg .u64 t; cvta.to.shared.u64 t, %1; cvt.u32.u64 %0, t; }" : "=r"(a) : "l"(p));
    return a;
}
__device__ __forceinline__ void ldsm4(uint32_t* r, uint32_t addr) {
    asm volatile("ldmatrix.sync.aligned.m8n8.x4.shared.b16 {%0,%1,%2,%3}, [%4];"
                 : "=r"(r[0]), "=r"(r[1]), "=r"(r[2]), "=r"(r[3]) : "r"(addr));
}
__device__ __forceinline__ void mma16816(float* c, const uint32_t* a, uint32_t b0, uint32_t b1) {
    asm("mma.sync.aligned.m16n8k16.row.col.f32.bf16.bf16.f32 "
        "{%0,%1,%2,%3}, {%4,%5,%6,%7}, {%8,%9}, {%0,%1,%2,%3};"
        : "+f"(c[0]), "+f"(c[1]), "+f"(c[2]), "+f"(c[3])
        : "r"(a[0]), "r"(a[1]), "r"(a[2]), "r"(a[3]), "r"(b0), "r"(b1));
}
__device__ __forceinline__ void split2(float a, float b, uint32_t& hi, uint32_t& lo) {
    __nv_bfloat16 ah = __float2bfloat16(a), bh = __float2bfloat16(b);
    float al = a - __bfloat162float(ah);
    float bl = b - __bfloat162float(bh);
    __nv_bfloat162 H; H.x = ah; H.y = bh;
    __nv_bfloat162 L; L.x = __float2bfloat16(al); L.y = __float2bfloat16(bl);
    hi = *reinterpret_cast<uint32_t*>(&H);
    lo = *reinterpret_cast<uint32_t*>(&L);
}
__device__ __forceinline__ void cpasync16(uint32_t dst, const void* src) {
    asm volatile("cp.async.cg.shared.global [%0], [%1], 16;" :: "r"(dst), "l"(src));
}
#define CP_COMMIT() asm volatile("cp.async.commit_group;" ::: "memory")
#define CP_WAIT0()  asm volatile("cp.async.wait_group 0;" ::: "memory")
__device__ __forceinline__ uint32_t prmt_hi(uint32_t a, uint32_t b) {
    uint32_t d;
    asm("prmt.b32 %0, %1, %2, 0x7632;" : "=r"(d) : "r"(a), "r"(b));
    return d;
}
__device__ __forceinline__ uint32_t cvt_bf16x2(float hi, float lo) {
    uint32_t d;
    asm("cvt.rn.bf16x2.f32 %0, %1, %2;" : "=r"(d) : "f"(hi), "f"(lo));
    return d;
}

// ---------------- Prepass ----------------
__global__ void prep_q(const float* __restrict__ q) {
    int idx = blockIdx.x * 256 + threadIdx.x;
    float4 x = ((const float4*)q)[idx];
    x.x *= 0.125f; x.y *= 0.125f; x.z *= 0.125f; x.w *= 0.125f;
    uint32_t h0, l0, h1, l1;
    split2(x.x, x.y, h0, l0);
    split2(x.z, x.w, h1, l1);
    ((uint2*)g_Qh)[idx] = make_uint2(h0, h1);
    ((uint2*)g_Ql)[idx] = make_uint2(l0, l1);
}
__global__ void prep_k(const float* __restrict__ k) {
    int idx = blockIdx.x * 256 + threadIdx.x;
    float4 x = ((const float4*)k)[idx];
    uint32_t h0, l0, h1, l1;
    split2(x.x, x.y, h0, l0);
    split2(x.z, x.w, h1, l1);
    ((uint2*)g_Kh)[idx] = make_uint2(h0, h1);
    ((uint2*)g_Kl)[idx] = make_uint2(l0, l1);
}
__global__ void prep_v(const float* __restrict__ v) {
    __shared__ float vs[128 * 65];
    const int b = blockIdx.x >> 4, st = blockIdx.x & 15, tid = threadIdx.x;
    const float4* vp = (const float4*)(v + ((size_t)(b * LSEQ + st * 128)) * DH);
#pragma unroll
    for (int it = 0; it < 8; ++it) {
        int fi = it * 256 + tid;
        int s = fi >> 4, d4 = fi & 15;
        float4 x = vp[fi];
        vs[s * 65 + d4 * 4 + 0] = x.x;
        vs[s * 65 + d4 * 4 + 1] = x.y;
        vs[s * 65 + d4 * 4 + 2] = x.z;
        vs[s * 65 + d4 * 4 + 3] = x.w;
    }
    __syncthreads();
#pragma unroll
    for (int it = 0; it < 4; ++it) {
        int fo = it * 256 + tid;
        int d = fo >> 4, cu = fo & 15;
        float vv[8];
#pragma unroll
        for (int j = 0; j < 8; ++j) vv[j] = vs[(cu * 8 + j) * 65 + d];
        uint32_t hw[4], lw[4];
#pragma unroll
        for (int j = 0; j < 4; ++j) split2(vv[2 * j], vv[2 * j + 1], hw[j], lw[j]);
        size_t o = ((size_t)(b * DH + d)) * LSEQ + st * 128 + cu * 8;
        *(uint4*)(g_Vth + o) = make_uint4(hw[0], hw[1], hw[2], hw[3]);
        *(uint4*)(g_Vtl + o) = make_uint4(lw[0], lw[1], lw[2], lw[3]);
    }
}

// ---------------- Fused attention (128 threads, 4 warps, 64 q-rows/CTA) ----------------
// smem: Q hi 0..8K, Q lo 8K..16K
//       K bufs: SK0 16K..32K, SK1 32K..48K  (each = hi 8K + lo 8K; sweep1 uses hi half only)
//       V bufs: SV0 48K..64K, SV1 64K..80K  (each = hi 8K + lo 8K)
//       lzs 80K (512B). Total 82432 -> 2 CTAs/SM.
#define SQH 0
#define SQL 8192
#define SK(i) (16384 + (i) * 16384)
#define SV(i) (49152 + (i) * 16384)
#define SLZ 81920
#define SMEM_TOT 82432

__global__ void __launch_bounds__(128, 2)
sdpa_fused(float* __restrict__ attn, float* __restrict__ lattn, float* __restrict__ outp) {
    extern __shared__ char sm[];
    const uint32_t sb = smem_u32(sm);
    const int tid = threadIdx.x, lane = tid & 31, w = tid >> 5;   // w in 0..3
    const int b = blockIdx.y, qbase = blockIdx.x * 64;

    const int arow = lane & 15, achk = lane >> 4;
    const int brow = ((lane >> 4) << 3) + (lane & 7), bch = (lane >> 3) & 1;
    const int rq = lane >> 2, qd = lane & 3;

    const char* kh_base = (const char*)(g_Kh + (size_t)b * LSEQ * DH);
    const char* kl_base = (const char*)(g_Kl + (size_t)b * LSEQ * DH);
    const char* vh_base = (const char*)(g_Vth + (size_t)b * DH * LSEQ);
    const char* vl_base = (const char*)(g_Vtl + (size_t)b * DH * LSEQ);

    // K chunk u, hi only (sweep 1)
#define LOAD_KH(buf, u) do {                                                   \
        const char* _sh = kh_base + (size_t)(u) * 8192;                        \
        _Pragma("unroll")                                                      \
        for (int r = 0; r < 4; ++r) {                                          \
            int fo = r * 128 + tid;                                            \
            int row = fo >> 3, cu = fo & 7;                                    \
            uint32_t off = (uint32_t)row * 128 + ((cu ^ (row & 7)) << 4);      \
            cpasync16(sb + (buf) + off, _sh + fo * 16);                        \
        }                                                                      \
    } while (0)

    // K chunk u, hi + lo (sweep 2)
#define LOAD_K(buf, u) do {                                                    \
        const char* _sh = kh_base + (size_t)(u) * 8192;                        \
        const char* _sl = kl_base + (size_t)(u) * 8192;                        \
        _Pragma("unroll")                                                      \
        for (int r = 0; r < 4; ++r) {                                          \
            int fo = r * 128 + tid;                                            \
            int row = fo >> 3, cu = fo & 7;                                    \
            uint32_t off = (uint32_t)row * 128 + ((cu ^ (row & 7)) << 4);      \
            cpasync16(sb + (buf) + off, _sh + fo * 16);                        \
            cpasync16(sb + (buf) + 8192 + off, _sl + fo * 16);                 \
        }                                                                      \
    } while (0)

    // V chunk u: d rows 0..63, seq cols u*64..u*64+63
#define LOAD_V(buf, u) do {                                                    \
        _Pragma("unroll")                                                      \
        for (int r = 0; r < 4; ++r) {                                          \
            int fo = r * 128 + tid;                                            \
            int row = fo >> 3, cu = fo & 7;                                    \
            uint32_t off = (uint32_t)row * 128 + ((cu ^ (row & 7)) << 4);      \
            size_t sof = (size_t)row * (LSEQ * 2) + (size_t)(u) * 128 + cu * 16; \
            cpasync16(sb + (buf) + off, vh_base + sof);                        \
            cpasync16(sb + (buf) + 8192 + off, vl_base + sof);                 \
        }                                                                      \
    } while (0)

    // ---- prologue: Q tile (64x64, hi+lo) + K chunk 0 (hi only) ----
    {
        const char* qh = (const char*)(g_Qh + (size_t)(b * LSEQ + qbase) * DH);
        const char* ql = (const char*)(g_Ql + (size_t)(b * LSEQ + qbase) * DH);
#pragma unroll
        for (int r = 0; r < 4; ++r) {
            int fo = r * 128 + tid;
            int row = fo >> 3, cu = fo & 7;
            uint32_t off = (uint32_t)row * 128 + ((cu ^ (row & 7)) << 4);
            cpasync16(sb + SQH + off, qh + fo * 16);
            cpasync16(sb + SQL + off, ql + fo * 16);
        }
        LOAD_KH(SK(0), 0);
        CP_COMMIT();
    }

    uint32_t aQh[4][4], aQl[4][4];
    float lrun[2] = {0.f, 0.f};

    // 1-term QK (sweep 1): Qh*Kh only, distance-4 accumulator pairing.
#define COMPUTE_QK1(c, kb) do {                                                \
        _Pragma("unroll")                                                      \
        for (int nt = 0; nt < 8; ++nt) {                                       \
            c[nt][0] = 0.f; c[nt][1] = 0.f; c[nt][2] = 0.f; c[nt][3] = 0.f;    \
        }                                                                      \
        _Pragma("unroll")                                                      \
        for (int ks = 0; ks < 4; ++ks) {                                       \
            _Pragma("unroll")                                                  \
            for (int pp = 0; pp < 2; ++pp) {                                   \
                int row0 = pp * 32 + brow;                                     \
                int row1 = row0 + 16;                                          \
                uint32_t ad0 = sb + (kb) + row0 * 128 +                        \
                               (((ks * 2 + bch) ^ (row0 & 7)) << 4);           \
                uint32_t ad1 = sb + (kb) + row1 * 128 +                        \
                               (((ks * 2 + bch) ^ (row1 & 7)) << 4);           \
                uint32_t bh0[4], bh1[4];                                       \
                ldsm4(bh0, ad0);                                               \
                ldsm4(bh1, ad1);                                               \
                mma16816(c[4*pp+0], aQh[ks], bh0[0], bh0[1]);                  \
                mma16816(c[4*pp+1], aQh[ks], bh0[2], bh0[3]);                  \
                mma16816(c[4*pp+2], aQh[ks], bh1[0], bh1[1]);                  \
                mma16816(c[4*pp+3], aQh[ks], bh1[2], bh1[3]);                  \
            }                                                                  \
        }                                                                      \
    } while (0)

    // 3-term QK (sweep 2)
#define COMPUTE_QK3(c, kb) do {                                                \
        _Pragma("unroll")                                                      \
        for (int nt = 0; nt < 8; ++nt) {                                       \
            c[nt][0] = 0.f; c[nt][1] = 0.f; c[nt][2] = 0.f; c[nt][3] = 0.f;    \
        }                                                                      \
        _Pragma("unroll")                                                      \
        for (int ks = 0; ks < 4; ++ks) {                                       \
            _Pragma("unroll")                                                  \
            for (int pp = 0; pp < 2; ++pp) {                                   \
                int row0 = pp * 32 + brow;                                     \
                int row1 = row0 + 16;                                          \
                uint32_t ad0 = sb + (kb) + row0 * 128 +                        \
                               (((ks * 2 + bch) ^ (row0 & 7)) << 4);           \
                uint32_t ad1 = sb + (kb) + row1 * 128 +                        \
                               (((ks * 2 + bch) ^ (row1 & 7)) << 4);           \
                uint32_t bh0[4], bh1[4], bl0[4], bl1[4];                       \
                ldsm4(bh0, ad0);                                               \
                ldsm4(bh1, ad1);                                               \
                ldsm4(bl0, ad0 + 8192);                                        \
                ldsm4(bl1, ad1 + 8192);                                        \
                mma16816(c[4*pp+0], aQh[ks], bh0[0], bh0[1]);                  \
                mma16816(c[4*pp+1], aQh[ks], bh0[2], bh0[3]);                  \
                mma16816(c[4*pp+2], aQh[ks], bh1[0], bh1[1]);                  \
                mma16816(c[4*pp+3], aQh[ks], bh1[2], bh1[3]);                  \
                mma16816(c[4*pp+0], aQh[ks], bl0[0], bl0[1]);                  \
                mma16816(c[4*pp+1], aQh[ks], bl0[2], bl0[3]);                  \
                mma16816(c[4*pp+2], aQh[ks], bl1[0], bl1[1]);                  \
                mma16816(c[4*pp+3], aQh[ks], bl1[2], bl1[3]);                  \
                mma16816(c[4*pp+0], aQl[ks], bh0[0], bh0[1]);                  \
                mma16816(c[4*pp+1], aQl[ks], bh0[2], bh0[3]);                  \
                mma16816(c[4*pp+2], aQl[ks], bh1[0], bh1[1]);                  \
                mma16816(c[4*pp+3], aQl[ks], bh1[2], bh1[3]);                  \
            }                                                                  \
        }                                                                      \
    } while (0)

    // ================= Sweep 1: sumexp only (fixed offset 0, no max) =================
    for (int u = 0; u < 32; ++u) {
        CP_WAIT0();
        __syncthreads();
        if (u < 31) {
            LOAD_KH(SK((u + 1) & 1), u + 1);
            CP_COMMIT();
        }
        if (u == 0) {
#pragma unroll
            for (int ks = 0; ks < 4; ++ks) {
                int row = w * 16 + arow;
                uint32_t ad = sb + SQH + row * 128 + (((ks * 2 + achk) ^ (row & 7)) << 4);
                ldsm4(aQh[ks], ad);
            }
        }
        float c[8][4];
        COMPUTE_QK1(c, SK(u & 1));
#pragma unroll
        for (int h = 0; h < 2; ++h) {
            float sum = 0.f;
#pragma unroll
            for (int nt = 0; nt < 8; ++nt)
                sum += __expf(c[nt][2 * h]) + __expf(c[nt][2 * h + 1]);
            lrun[h] += sum;
        }
    }

    // ---- logZ = log(sum): quad reduce ----
    float* lzs = (float*)(sm + SLZ);
#pragma unroll
    for (int h = 0; h < 2; ++h) {
        float l = lrun[h];
        l += __shfl_xor_sync(0xffffffffu, l, 1);
        l += __shfl_xor_sync(0xffffffffu, l, 2);
        if (qd == 0) lzs[w * 16 + rq + 8 * h] = logf(l);
    }
    __syncwarp();
    const float lz0 = lzs[w * 16 + rq];
    const float lz1 = lzs[w * 16 + rq + 8];

    // ================= Sweep 2: 3-term QK, emit, PV =================
    float o[8][4];
#pragma unroll
    for (int g = 0; g < 8; ++g)
#pragma unroll
        for (int j = 0; j < 4; ++j) o[g][j] = 0.f;

    __syncthreads();
    LOAD_K(SK(0), 0);
    LOAD_V(SV(0), 0);
    CP_COMMIT();

    // load Q-lo fragments (Q-hi already resident)
#pragma unroll
    for (int ks = 0; ks < 4; ++ks) {
        int row = w * 16 + arow;
        uint32_t ad = sb + SQL + row * 128 + (((ks * 2 + achk) ^ (row & 7)) << 4);
        ldsm4(aQl[ks], ad);
    }

    float* aRow = attn + ((size_t)(b * LSEQ + qbase + w * 16 + rq)) * LSEQ + qd * 2;
    float* lRow = lattn + ((size_t)(b * LSEQ + qbase + w * 16 + rq)) * LSEQ + qd * 2;

    for (int u = 0; u < 32; ++u) {
        CP_WAIT0();
        __syncthreads();
        if (u < 31) {
            LOAD_K(SK((u + 1) & 1), u + 1);
            LOAD_V(SV((u + 1) & 1), u + 1);
            CP_COMMIT();
        }

        float c[8][4];
        COMPUTE_QK3(c, SK(u & 1));

        // convert: attn/lattn stores + register-resident P fragments (64 cols)
        uint32_t aPh[4][4], aPl[4][4];
        float* aT = aRow + u * 64;
        float* lT = lRow + u * 64;
#pragma unroll
        for (int kc = 0; kc < 4; ++kc) {
#pragma unroll
            for (int qq = 0; qq < 2; ++qq) {
                const int nt = 2 * kc + qq;
                float la0 = c[nt][0] - lz0, la1 = c[nt][1] - lz0;
                float la2 = c[nt][2] - lz1, la3 = c[nt][3] - lz1;
                float p0 = __expf(la0), p1 = __expf(la1);
                float p2 = __expf(la2), p3 = __expf(la3);
                *(float2*)(aT + nt * 8) = make_float2(p0, p1);
                *(float2*)(aT + 8 * LSEQ + nt * 8) = make_float2(p2, p3);
                *(float2*)(lT + nt * 8) = make_float2(la0, la1);
                *(float2*)(lT + 8 * LSEQ + nt * 8) = make_float2(la2, la3);
                uint32_t u0 = __float_as_uint(p0), u1 = __float_as_uint(p1);
                uint32_t u2 = __float_as_uint(p2), u3 = __float_as_uint(p3);
                aPh[kc][qq * 2 + 0] = prmt_hi(u0, u1);
                aPh[kc][qq * 2 + 1] = prmt_hi(u2, u3);
                aPl[kc][qq * 2 + 0] = cvt_bf16x2(p1 - __uint_as_float(u1 & 0xFFFF0000u),
                                                 p0 - __uint_as_float(u0 & 0xFFFF0000u));
                aPl[kc][qq * 2 + 1] = cvt_bf16x2(p3 - __uint_as_float(u3 & 0xFFFF0000u),
                                                 p2 - __uint_as_float(u2 & 0xFFFF0000u));
            }
        }

        // PV over this 64-kv chunk: O += Ph*Vh + Ph*Vl + Pl*Vh
        const uint32_t vb = sb + SV(u & 1);
#pragma unroll
        for (int kc = 0; kc < 4; ++kc) {
#pragma unroll
            for (int gg = 0; gg < 2; ++gg) {
                int row0 = gg * 32 + brow;     // d rows
                int row1 = row0 + 16;
                uint32_t ad0 = vb + row0 * 128 + (((kc * 2 + bch) ^ (row0 & 7)) << 4);
                uint32_t ad1 = vb + row1 * 128 + (((kc * 2 + bch) ^ (row1 & 7)) << 4);
                uint32_t vh0[4], vh1[4], vl0[4], vl1[4];
                ldsm4(vh0, ad0);
                ldsm4(vh1, ad1);
                ldsm4(vl0, ad0 + 8192);
                ldsm4(vl1, ad1 + 8192);
                mma16816(o[4*gg+0], aPh[kc], vh0[0], vh0[1]);
                mma16816(o[4*gg+1], aPh[kc], vh0[2], vh0[3]);
                mma16816(o[4*gg+2], aPh[kc], vh1[0], vh1[1]);
                mma16816(o[4*gg+3], aPh[kc], vh1[2], vh1[3]);
                mma16816(o[4*gg+0], aPh[kc], vl0[0], vl0[1]);
                mma16816(o[4*gg+1], aPh[kc], vl0[2], vl0[3]);
                mma16816(o[4*gg+2], aPh[kc], vl1[0], vl1[1]);
                mma16816(o[4*gg+3], aPh[kc], vl1[2], vl1[3]);
                mma16816(o[4*gg+0], aPl[kc], vh0[0], vh0[1]);
                mma16816(o[4*gg+1], aPl[kc], vh0[2], vh0[3]);
                mma16816(o[4*gg+2], aPl[kc], vh1[0], vh1[1]);
                mma16816(o[4*gg+3], aPl[kc], vh1[2], vh1[3]);
            }
        }
    }

    // ---- head-folded output ----
    {
        int qr = qbase + w * 16 + rq;
        float* dp = outp + (size_t)qr * (DH * BH) + b * DH + qd * 2;
#pragma unroll
        for (int g = 0; g < 8; ++g) {
            *(float2*)(dp + g * 8) = make_float2(o[g][0], o[g][1]);
            *(float2*)(dp + 8 * (DH * BH) + g * 8) = make_float2(o[g][2], o[g][3]);
        }
    }
}

extern "C" void kernel_launch(void* const* d_in, const int* in_sizes, int n_in,
                              void* d_out, int out_size) {
    const float* q = (const float*)d_in[0];
    const float* k = (const float*)d_in[1];
    const float* v = (const float*)d_in[2];

    float* outp = (float*)d_out;
    float* attn = outp + OUT_ELE;
    float* lattn = attn + ATT_ELE;

    cudaFuncSetAttribute(sdpa_fused, cudaFuncAttributeMaxDynamicSharedMemorySize, SMEM_TOT);

    prep_q<<<2048, 256>>>(q);
    prep_k<<<2048, 256>>>(k);
    prep_v<<<256, 256>>>(v);

    dim3 grid(LSEQ / 64, BH);
    sdpa_fused<<<grid, 128, SMEM_TOT>>>(attn, lattn, outp);
}

// round 14
// speedup vs baseline: 1.6512x; 1.2151x over previous
#include <cuda_runtime.h>
#include <cuda_fp16.h>
#include <cstdint>
#include <math.h>

#define BH 16
#define LSEQ 2048
#define DH 64
#define OUT_ELE (LSEQ * DH * BH)
#define ATT_ELE ((size_t)BH * LSEQ * LSEQ)

__device__ __half g_Qh[BH * LSEQ * DH];
__device__ __half g_Ql[BH * LSEQ * DH];
__device__ __half g_Kf[BH * LSEQ * DH];
__device__ __half g_Vtf[BH * DH * LSEQ];

__device__ __forceinline__ uint32_t smem_u32(const void* p) {
    uint32_t a;
    asm("{ .reg .u64 t; cvta.to.shared.u64 t, %1; cvt.u32.u64 %0, t; }" : "=r"(a) : "l"(p));
    return a;
}
__device__ __forceinline__ void ldsm4(uint32_t* r, uint32_t addr) {
    asm volatile("ldmatrix.sync.aligned.m8n8.x4.shared.b16 {%0,%1,%2,%3}, [%4];"
                 : "=r"(r[0]), "=r"(r[1]), "=r"(r[2]), "=r"(r[3]) : "r"(addr));
}
__device__ __forceinline__ void mma16816(float* c, const uint32_t* a, uint32_t b0, uint32_t b1) {
    asm("mma.sync.aligned.m16n8k16.row.col.f32.f16.f16.f32 "
        "{%0,%1,%2,%3}, {%4,%5,%6,%7}, {%8,%9}, {%0,%1,%2,%3};"
        : "+f"(c[0]), "+f"(c[1]), "+f"(c[2]), "+f"(c[3])
        : "r"(a[0]), "r"(a[1]), "r"(a[2]), "r"(a[3]), "r"(b0), "r"(b1));
}
__device__ __forceinline__ void split2h(float a, float b, uint32_t& hi, uint32_t& lo) {
    __half ah = __float2half_rn(a), bh = __float2half_rn(b);
    __half al = __float2half_rn(a - __half2float(ah));
    __half bl = __float2half_rn(b - __half2float(bh));
    __half2 H = __halves2half2(ah, bh);
    __half2 L = __halves2half2(al, bl);
    hi = *reinterpret_cast<uint32_t*>(&H);
    lo = *reinterpret_cast<uint32_t*>(&L);
}
__device__ __forceinline__ uint32_t pack2h(float a, float b) {
    __half2 H = __halves2half2(__float2half_rn(a), __float2half_rn(b));
    return *reinterpret_cast<uint32_t*>(&H);
}
__device__ __forceinline__ void cpasync16(uint32_t dst, const void* src) {
    asm volatile("cp.async.cg.shared.global [%0], [%1], 16;" :: "r"(dst), "l"(src));
}
#define CP_COMMIT() asm volatile("cp.async.commit_group;" ::: "memory")
#define CP_WAIT0()  asm volatile("cp.async.wait_group 0;" ::: "memory")

// ---------------- Prepass ----------------
__global__ void prep_q(const float* __restrict__ q) {
    int idx = blockIdx.x * 256 + threadIdx.x;
    float4 x = ((const float4*)q)[idx];
    x.x *= 0.125f; x.y *= 0.125f; x.z *= 0.125f; x.w *= 0.125f;
    uint32_t h0, l0, h1, l1;
    split2h(x.x, x.y, h0, l0);
    split2h(x.z, x.w, h1, l1);
    ((uint2*)g_Qh)[idx] = make_uint2(h0, h1);
    ((uint2*)g_Ql)[idx] = make_uint2(l0, l1);
}
__global__ void prep_k(const float* __restrict__ k) {
    int idx = blockIdx.x * 256 + threadIdx.x;
    float4 x = ((const float4*)k)[idx];
    ((uint2*)g_Kf)[idx] = make_uint2(pack2h(x.x, x.y), pack2h(x.z, x.w));
}
__global__ void prep_v(const float* __restrict__ v) {
    __shared__ float vs[128 * 65];
    const int b = blockIdx.x >> 4, st = blockIdx.x & 15, tid = threadIdx.x;
    const float4* vp = (const float4*)(v + ((size_t)(b * LSEQ + st * 128)) * DH);
#pragma unroll
    for (int it = 0; it < 8; ++it) {
        int fi = it * 256 + tid;
        int s = fi >> 4, d4 = fi & 15;
        float4 x = vp[fi];
        vs[s * 65 + d4 * 4 + 0] = x.x;
        vs[s * 65 + d4 * 4 + 1] = x.y;
        vs[s * 65 + d4 * 4 + 2] = x.z;
        vs[s * 65 + d4 * 4 + 3] = x.w;
    }
    __syncthreads();
#pragma unroll
    for (int it = 0; it < 4; ++it) {
        int fo = it * 256 + tid;
        int d = fo >> 4, cu = fo & 15;
        uint32_t hw[4];
#pragma unroll
        for (int j = 0; j < 4; ++j)
            hw[j] = pack2h(vs[(cu * 8 + 2 * j) * 65 + d], vs[(cu * 8 + 2 * j + 1) * 65 + d]);
        size_t o = ((size_t)(b * DH + d)) * LSEQ + st * 128 + cu * 8;
        *(uint4*)(g_Vtf + o) = make_uint4(hw[0], hw[1], hw[2], hw[3]);
    }
}

// ---------------- Fused attention (128 threads, 4 warps, 64 q-rows/CTA) ----------------
// smem: Q hi 0..8K, Q lo 8K..16K
//       K bufs: SK0 16K..24K, SK1 24K..32K  (single fp16; 64 seq x 64 d)
//       V bufs: SV0 32K..40K, SV1 40K..48K  (single fp16; 64 d x 64 seq)
//       lzs 48K (512B). Total 49664 -> 2 CTAs/SM.
#define SQH 0
#define SQL 8192
#define SK(i) (16384 + (i) * 8192)
#define SV(i) (32768 + (i) * 8192)
#define SLZ 49152
#define SMEM_TOT 49664

__global__ void __launch_bounds__(128, 2)
sdpa_fused(float* __restrict__ attn, float* __restrict__ lattn, float* __restrict__ outp) {
    extern __shared__ char sm[];
    const uint32_t sb = smem_u32(sm);
    const int tid = threadIdx.x, lane = tid & 31, w = tid >> 5;   // w in 0..3
    const int b = blockIdx.y, qbase = blockIdx.x * 64;

    const int arow = lane & 15, achk = lane >> 4;
    const int brow = ((lane >> 4) << 3) + (lane & 7), bch = (lane >> 3) & 1;
    const int rq = lane >> 2, qd = lane & 3;

    const char* kf_base = (const char*)(g_Kf + (size_t)b * LSEQ * DH);
    const char* vf_base = (const char*)(g_Vtf + (size_t)b * DH * LSEQ);

    // K chunk u: seq rows u*64..u*64+63, 64 d. 8KB.
#define LOAD_K(buf, u) do {                                                    \
        const char* _s = kf_base + (size_t)(u) * 8192;                         \
        _Pragma("unroll")                                                      \
        for (int r = 0; r < 4; ++r) {                                          \
            int fo = r * 128 + tid;                                            \
            int row = fo >> 3, cu = fo & 7;                                    \
            uint32_t off = (uint32_t)row * 128 + ((cu ^ (row & 7)) << 4);      \
            cpasync16(sb + (buf) + off, _s + fo * 16);                         \
        }                                                                      \
    } while (0)

    // V chunk u: d rows 0..63, seq cols u*64..u*64+63. 8KB.
#define LOAD_V(buf, u) do {                                                    \
        _Pragma("unroll")                                                      \
        for (int r = 0; r < 4; ++r) {                                          \
            int fo = r * 128 + tid;                                            \
            int row = fo >> 3, cu = fo & 7;                                    \
            uint32_t off = (uint32_t)row * 128 + ((cu ^ (row & 7)) << 4);      \
            size_t sof = (size_t)row * (LSEQ * 2) + (size_t)(u) * 128 + cu * 16; \
            cpasync16(sb + (buf) + off, vf_base + sof);                        \
        }                                                                      \
    } while (0)

    // ---- prologue: Q tile (64x64, hi+lo) + K chunk 0 ----
    {
        const char* qh = (const char*)(g_Qh + (size_t)(b * LSEQ + qbase) * DH);
        const char* ql = (const char*)(g_Ql + (size_t)(b * LSEQ + qbase) * DH);
#pragma unroll
        for (int r = 0; r < 4; ++r) {
            int fo = r * 128 + tid;
            int row = fo >> 3, cu = fo & 7;
            uint32_t off = (uint32_t)row * 128 + ((cu ^ (row & 7)) << 4);
            cpasync16(sb + SQH + off, qh + fo * 16);
            cpasync16(sb + SQL + off, ql + fo * 16);
        }
        LOAD_K(SK(0), 0);
        CP_COMMIT();
    }

    uint32_t aQh[4][4], aQl[4][4];
    float lrun[2] = {0.f, 0.f};

    // 1-term QK (sweep 1): Qh*Kf, distance-4 accumulator pairing.
#define COMPUTE_QK1(c, kb) do {                                                \
        _Pragma("unroll")                                                      \
        for (int nt = 0; nt < 8; ++nt) {                                       \
            c[nt][0] = 0.f; c[nt][1] = 0.f; c[nt][2] = 0.f; c[nt][3] = 0.f;    \
        }                                                                      \
        _Pragma("unroll")                                                      \
        for (int ks = 0; ks < 4; ++ks) {                                       \
            _Pragma("unroll")                                                  \
            for (int pp = 0; pp < 2; ++pp) {                                   \
                int row0 = pp * 32 + brow;                                     \
                int row1 = row0 + 16;                                          \
                uint32_t ad0 = sb + (kb) + row0 * 128 +                        \
                               (((ks * 2 + bch) ^ (row0 & 7)) << 4);           \
                uint32_t ad1 = sb + (kb) + row1 * 128 +                        \
                               (((ks * 2 + bch) ^ (row1 & 7)) << 4);           \
                uint32_t b0[4], b1[4];                                         \
                ldsm4(b0, ad0);                                                \
                ldsm4(b1, ad1);                                                \
                mma16816(c[4*pp+0], aQh[ks], b0[0], b0[1]);                    \
                mma16816(c[4*pp+1], aQh[ks], b0[2], b0[3]);                    \
                mma16816(c[4*pp+2], aQh[ks], b1[0], b1[1]);                    \
                mma16816(c[4*pp+3], aQh[ks], b1[2], b1[3]);                    \
            }                                                                  \
        }                                                                      \
    } while (0)

    // 2-term QK (sweep 2): (Qh + Ql)*Kf
#define COMPUTE_QK2(c, kb) do {                                                \
        _Pragma("unroll")                                                      \
        for (int nt = 0; nt < 8; ++nt) {                                       \
            c[nt][0] = 0.f; c[nt][1] = 0.f; c[nt][2] = 0.f; c[nt][3] = 0.f;    \
        }                                                                      \
        _Pragma("unroll")                                                      \
        for (int ks = 0; ks < 4; ++ks) {                                       \
            _Pragma("unroll")                                                  \
            for (int pp = 0; pp < 2; ++pp) {                                   \
                int row0 = pp * 32 + brow;                                     \
                int row1 = row0 + 16;                                          \
                uint32_t ad0 = sb + (kb) + row0 * 128 +                        \
                               (((ks * 2 + bch) ^ (row0 & 7)) << 4);           \
                uint32_t ad1 = sb + (kb) + row1 * 128 +                        \
                               (((ks * 2 + bch) ^ (row1 & 7)) << 4);           \
                uint32_t b0[4], b1[4];                                         \
                ldsm4(b0, ad0);                                                \
                ldsm4(b1, ad1);                                                \
                mma16816(c[4*pp+0], aQh[ks], b0[0], b0[1]);                    \
                mma16816(c[4*pp+1], aQh[ks], b0[2], b0[3]);                    \
                mma16816(c[4*pp+2], aQh[ks], b1[0], b1[1]);                    \
                mma16816(c[4*pp+3], aQh[ks], b1[2], b1[3]);                    \
                mma16816(c[4*pp+0], aQl[ks], b0[0], b0[1]);                    \
                mma16816(c[4*pp+1], aQl[ks], b0[2], b0[3]);                    \
                mma16816(c[4*pp+2], aQl[ks], b1[0], b1[1]);                    \
                mma16816(c[4*pp+3], aQl[ks], b1[2], b1[3]);                    \
            }                                                                  \
        }                                                                      \
    } while (0)

    // ================= Sweep 1: sumexp only (fixed offset 0) =================
    for (int u = 0; u < 32; ++u) {
        CP_WAIT0();
        __syncthreads();
        if (u < 31) {
            LOAD_K(SK((u + 1) & 1), u + 1);
            CP_COMMIT();
        }
        if (u == 0) {
#pragma unroll
            for (int ks = 0; ks < 4; ++ks) {
                int row = w * 16 + arow;
                uint32_t ad = sb + SQH + row * 128 + (((ks * 2 + achk) ^ (row & 7)) << 4);
                ldsm4(aQh[ks], ad);
            }
        }
        float c[8][4];
        COMPUTE_QK1(c, SK(u & 1));
#pragma unroll
        for (int h = 0; h < 2; ++h) {
            float sum = 0.f;
#pragma unroll
            for (int nt = 0; nt < 8; ++nt)
                sum += __expf(c[nt][2 * h]) + __expf(c[nt][2 * h + 1]);
            lrun[h] += sum;
        }
    }

    // ---- logZ = log(sum): quad reduce ----
    float* lzs = (float*)(sm + SLZ);
#pragma unroll
    for (int h = 0; h < 2; ++h) {
        float l = lrun[h];
        l += __shfl_xor_sync(0xffffffffu, l, 1);
        l += __shfl_xor_sync(0xffffffffu, l, 2);
        if (qd == 0) lzs[w * 16 + rq + 8 * h] = logf(l);
    }
    __syncwarp();
    const float lz0 = lzs[w * 16 + rq];
    const float lz1 = lzs[w * 16 + rq + 8];

    // ================= Sweep 2: 2-term QK, emit, 2-term PV =================
    float o[8][4];
#pragma unroll
    for (int g = 0; g < 8; ++g)
#pragma unroll
        for (int j = 0; j < 4; ++j) o[g][j] = 0.f;

    __syncthreads();
    LOAD_K(SK(0), 0);
    LOAD_V(SV(0), 0);
    CP_COMMIT();

    // load Q-lo fragments (Q-hi already resident)
#pragma unroll
    for (int ks = 0; ks < 4; ++ks) {
        int row = w * 16 + arow;
        uint32_t ad = sb + SQL + row * 128 + (((ks * 2 + achk) ^ (row & 7)) << 4);
        ldsm4(aQl[ks], ad);
    }

    float* aRow = attn + ((size_t)(b * LSEQ + qbase + w * 16 + rq)) * LSEQ + qd * 2;
    float* lRow = lattn + ((size_t)(b * LSEQ + qbase + w * 16 + rq)) * LSEQ + qd * 2;

    for (int u = 0; u < 32; ++u) {
        CP_WAIT0();
        __syncthreads();
        if (u < 31) {
            LOAD_K(SK((u + 1) & 1), u + 1);
            LOAD_V(SV((u + 1) & 1), u + 1);
            CP_COMMIT();
        }

        float c[8][4];
        COMPUTE_QK2(c, SK(u & 1));

        // convert: attn/lattn stores + register-resident P fragments (64 cols)
        uint32_t aPh[4][4], aPl[4][4];
        float* aT = aRow + u * 64;
        float* lT = lRow + u * 64;
#pragma unroll
        for (int kc = 0; kc < 4; ++kc) {
#pragma unroll
            for (int qq = 0; qq < 2; ++qq) {
                const int nt = 2 * kc + qq;
                float la0 = c[nt][0] - lz0, la1 = c[nt][1] - lz0;
                float la2 = c[nt][2] - lz1, la3 = c[nt][3] - lz1;
                float p0 = __expf(la0), p1 = __expf(la1);
                float p2 = __expf(la2), p3 = __expf(la3);
                *(float2*)(aT + nt * 8) = make_float2(p0, p1);
                *(float2*)(aT + 8 * LSEQ + nt * 8) = make_float2(p2, p3);
                *(float2*)(lT + nt * 8) = make_float2(la0, la1);
                *(float2*)(lT + 8 * LSEQ + nt * 8) = make_float2(la2, la3);
                // fp16 hi/lo split of P (hi = RN, lo = residual)
                __half h0 = __float2half_rn(p0), h1 = __float2half_rn(p1);
                __half h2 = __float2half_rn(p2), h3 = __float2half_rn(p3);
                __half2 H01 = __halves2half2(h0, h1), H23 = __halves2half2(h2, h3);
                aPh[kc][qq * 2 + 0] = *reinterpret_cast<uint32_t*>(&H01);
                aPh[kc][qq * 2 + 1] = *reinterpret_cast<uint32_t*>(&H23);
                __half2 L01 = __halves2half2(__float2half_rn(p0 - __half2float(h0)),
                                             __float2half_rn(p1 - __half2float(h1)));
                __half2 L23 = __halves2half2(__float2half_rn(p2 - __half2float(h2)),
                                             __float2half_rn(p3 - __half2float(h3)));
                aPl[kc][qq * 2 + 0] = *reinterpret_cast<uint32_t*>(&L01);
                aPl[kc][qq * 2 + 1] = *reinterpret_cast<uint32_t*>(&L23);
            }
        }

        // 2-term PV: O += (Ph + Pl) * Vf
        const uint32_t vb = sb + SV(u & 1);
#pragma unroll
        for (int kc = 0; kc < 4; ++kc) {
#pragma unroll
            for (int gg = 0; gg < 2; ++gg) {
                int row0 = gg * 32 + brow;     // d rows
                int row1 = row0 + 16;
                uint32_t ad0 = vb + row0 * 128 + (((kc * 2 + bch) ^ (row0 & 7)) << 4);
                uint32_t ad1 = vb + row1 * 128 + (((kc * 2 + bch) ^ (row1 & 7)) << 4);
                uint32_t v0[4], v1[4];
                ldsm4(v0, ad0);
                ldsm4(v1, ad1);
                mma16816(o[4*gg+0], aPh[kc], v0[0], v0[1]);
                mma16816(o[4*gg+1], aPh[kc], v0[2], v0[3]);
                mma16816(o[4*gg+2], aPh[kc], v1[0], v1[1]);
                mma16816(o[4*gg+3], aPh[kc], v1[2], v1[3]);
                mma16816(o[4*gg+0], aPl[kc], v0[0], v0[1]);
                mma16816(o[4*gg+1], aPl[kc], v0[2], v0[3]);
                mma16816(o[4*gg+2], aPl[kc], v1[0], v1[1]);
                mma16816(o[4*gg+3], aPl[kc], v1[2], v1[3]);
            }
        }
    }

    // ---- head-folded output ----
    {
        int qr = qbase + w * 16 + rq;
        float* dp = outp + (size_t)qr * (DH * BH) + b * DH + qd * 2;
#pragma unroll
        for (int g = 0; g < 8; ++g) {
            *(float2*)(dp + g * 8) = make_float2(o[g][0], o[g][1]);
            *(float2*)(dp + 8 * (DH * BH) + g * 8) = make_float2(o[g][2], o[g][3]);
        }
    }
}

extern "C" void kernel_launch(void* const* d_in, const int* in_sizes, int n_in,
                              void* d_out, int out_size) {
    const float* q = (const float*)d_in[0];
    const float* k = (const float*)d_in[1];
    const float* v = (const float*)d_in[2];

    float* outp = (float*)d_out;
    float* attn = outp + OUT_ELE;
    float* lattn = attn + ATT_ELE;

    cudaFuncSetAttribute(sdpa_fused, cudaFuncAttributeMaxDynamicSharedMemorySize, SMEM_TOT);

    prep_q<<<2048, 256>>>(q);
    prep_k<<<2048, 256>>>(k);
    prep_v<<<256, 256>>>(v);

    dim3 grid(LSEQ / 64, BH);
    sdpa_fused<<<grid, 128, SMEM_TOT>>>(attn, lattn, outp);
}

// round 15
// speedup vs baseline: 1.7222x; 1.0430x over previous
#include <cuda_runtime.h>
#include <cuda_fp16.h>
#include <cstdint>
#include <math.h>

#define BH 16
#define LSEQ 2048
#define DH 64
#define OUT_ELE (LSEQ * DH * BH)
#define ATT_ELE ((size_t)BH * LSEQ * LSEQ)

__device__ __half g_Qh[BH * LSEQ * DH];
__device__ __half g_Ql[BH * LSEQ * DH];
__device__ __half g_Kf[BH * LSEQ * DH];
__device__ __half g_Vtf[BH * DH * LSEQ];

__device__ __forceinline__ uint32_t smem_u32(const void* p) {
    uint32_t a;
    asm("{ .reg .u64 t; cvta.to.shared.u64 t, %1; cvt.u32.u64 %0, t; }" : "=r"(a) : "l"(p));
    return a;
}
__device__ __forceinline__ void ldsm4(uint32_t* r, uint32_t addr) {
    asm volatile("ldmatrix.sync.aligned.m8n8.x4.shared.b16 {%0,%1,%2,%3}, [%4];"
                 : "=r"(r[0]), "=r"(r[1]), "=r"(r[2]), "=r"(r[3]) : "r"(addr));
}
__device__ __forceinline__ void mma16816(float* c, const uint32_t* a, uint32_t b0, uint32_t b1) {
    asm("mma.sync.aligned.m16n8k16.row.col.f32.f16.f16.f32 "
        "{%0,%1,%2,%3}, {%4,%5,%6,%7}, {%8,%9}, {%0,%1,%2,%3};"
        : "+f"(c[0]), "+f"(c[1]), "+f"(c[2]), "+f"(c[3])
        : "r"(a[0]), "r"(a[1]), "r"(a[2]), "r"(a[3]), "r"(b0), "r"(b1));
}
__device__ __forceinline__ void split2h(float a, float b, uint32_t& hi, uint32_t& lo) {
    __half ah = __float2half_rn(a), bh = __float2half_rn(b);
    __half al = __float2half_rn(a - __half2float(ah));
    __half bl = __float2half_rn(b - __half2float(bh));
    __half2 H = __halves2half2(ah, bh);
    __half2 L = __halves2half2(al, bl);
    hi = *reinterpret_cast<uint32_t*>(&H);
    lo = *reinterpret_cast<uint32_t*>(&L);
}
__device__ __forceinline__ uint32_t pack2h(float a, float b) {
    __half2 H = __halves2half2(__float2half_rn(a), __float2half_rn(b));
    return *reinterpret_cast<uint32_t*>(&H);
}
__device__ __forceinline__ void cpasync16(uint32_t dst, const void* src) {
    asm volatile("cp.async.cg.shared.global [%0], [%1], 16;" :: "r"(dst), "l"(src));
}
#define CP_COMMIT() asm volatile("cp.async.commit_group;" ::: "memory")
#define CP_WAIT0()  asm volatile("cp.async.wait_group 0;" ::: "memory")

// ---------------- Prepass ----------------
__global__ void prep_q(const float* __restrict__ q) {
    int idx = blockIdx.x * 256 + threadIdx.x;
    float4 x = ((const float4*)q)[idx];
    x.x *= 0.125f; x.y *= 0.125f; x.z *= 0.125f; x.w *= 0.125f;
    uint32_t h0, l0, h1, l1;
    split2h(x.x, x.y, h0, l0);
    split2h(x.z, x.w, h1, l1);
    ((uint2*)g_Qh)[idx] = make_uint2(h0, h1);
    ((uint2*)g_Ql)[idx] = make_uint2(l0, l1);
}
__global__ void prep_k(const float* __restrict__ k) {
    int idx = blockIdx.x * 256 + threadIdx.x;
    float4 x = ((const float4*)k)[idx];
    ((uint2*)g_Kf)[idx] = make_uint2(pack2h(x.x, x.y), pack2h(x.z, x.w));
}
__global__ void prep_v(const float* __restrict__ v) {
    __shared__ float vs[128 * 65];
    const int b = blockIdx.x >> 4, st = blockIdx.x & 15, tid = threadIdx.x;
    const float4* vp = (const float4*)(v + ((size_t)(b * LSEQ + st * 128)) * DH);
#pragma unroll
    for (int it = 0; it < 8; ++it) {
        int fi = it * 256 + tid;
        int s = fi >> 4, d4 = fi & 15;
        float4 x = vp[fi];
        vs[s * 65 + d4 * 4 + 0] = x.x;
        vs[s * 65 + d4 * 4 + 1] = x.y;
        vs[s * 65 + d4 * 4 + 2] = x.z;
        vs[s * 65 + d4 * 4 + 3] = x.w;
    }
    __syncthreads();
#pragma unroll
    for (int it = 0; it < 4; ++it) {
        int fo = it * 256 + tid;
        int d = fo >> 4, cu = fo & 15;
        uint32_t hw[4];
#pragma unroll
        for (int j = 0; j < 4; ++j)
            hw[j] = pack2h(vs[(cu * 8 + 2 * j) * 65 + d], vs[(cu * 8 + 2 * j + 1) * 65 + d]);
        size_t o = ((size_t)(b * DH + d)) * LSEQ + st * 128 + cu * 8;
        *(uint4*)(g_Vtf + o) = make_uint4(hw[0], hw[1], hw[2], hw[3]);
    }
}

// ---------------- Fused attention (128 threads, 4 warps, 64 q-rows/CTA) ----------------
// kv chunk = 128. smem: Q hi 0..8K, Q lo 8K..16K
//   K bufs: SK0 16K..32K, SK1 32K..48K   (fp16, 128 seq x 64 d, 128B rows)
//   V bufs: SV0 48K..64K, SV1 64K..80K   (fp16, 64 d x 128 seq, 256B rows)
//   lzs 80K (512B). Total 82432 -> 2 CTAs/SM.
#define SQH 0
#define SQL 8192
#define SK(i) (16384 + (i) * 16384)
#define SV(i) (49152 + (i) * 16384)
#define SLZ 81920
#define SMEM_TOT 82432

__global__ void __launch_bounds__(128, 2)
sdpa_fused(float* __restrict__ attn, float* __restrict__ lattn, float* __restrict__ outp) {
    extern __shared__ char sm[];
    const uint32_t sb = smem_u32(sm);
    const int tid = threadIdx.x, lane = tid & 31, w = tid >> 5;   // w in 0..3
    const int b = blockIdx.y, qbase = blockIdx.x * 64;

    const int arow = lane & 15, achk = lane >> 4;
    const int brow = ((lane >> 4) << 3) + (lane & 7), bch = (lane >> 3) & 1;
    const int rq = lane >> 2, qd = lane & 3;

    const char* kf_base = (const char*)(g_Kf + (size_t)b * LSEQ * DH);
    const char* vf_base = (const char*)(g_Vtf + (size_t)b * DH * LSEQ);

    // K chunk u: seq rows u*128..u*128+127, 64 d. 16KB, 128B rows.
#define LOAD_K(buf, u) do {                                                    \
        const char* _s = kf_base + (size_t)(u) * 16384;                        \
        _Pragma("unroll")                                                      \
        for (int r = 0; r < 8; ++r) {                                          \
            int fo = r * 128 + tid;                                            \
            int row = fo >> 3, cu = fo & 7;                                    \
            uint32_t off = (uint32_t)row * 128 + ((cu ^ (row & 7)) << 4);      \
            cpasync16(sb + (buf) + off, _s + fo * 16);                         \
        }                                                                      \
    } while (0)

    // V chunk u: d rows 0..63, seq cols u*128..u*128+127. 16KB, 256B rows.
#define LOAD_V(buf, u) do {                                                    \
        _Pragma("unroll")                                                      \
        for (int r = 0; r < 8; ++r) {                                          \
            int fo = r * 128 + tid;                                            \
            int row = fo >> 4, cu = fo & 15;                                   \
            uint32_t off = (uint32_t)row * 256 + ((cu ^ (row & 15)) << 4);     \
            size_t sof = (size_t)row * (LSEQ * 2) + (size_t)(u) * 256 + cu * 16; \
            cpasync16(sb + (buf) + off, vf_base + sof);                        \
        }                                                                      \
    } while (0)

    // ---- prologue: Q tile (64x64, hi+lo) + K chunk 0 ----
    {
        const char* qh = (const char*)(g_Qh + (size_t)(b * LSEQ + qbase) * DH);
        const char* ql = (const char*)(g_Ql + (size_t)(b * LSEQ + qbase) * DH);
#pragma unroll
        for (int r = 0; r < 4; ++r) {
            int fo = r * 128 + tid;
            int row = fo >> 3, cu = fo & 7;
            uint32_t off = (uint32_t)row * 128 + ((cu ^ (row & 7)) << 4);
            cpasync16(sb + SQH + off, qh + fo * 16);
            cpasync16(sb + SQL + off, ql + fo * 16);
        }
        LOAD_K(SK(0), 0);
        CP_COMMIT();
    }

    uint32_t aQh[4][4], aQl[4][4];
    float lrun[2] = {0.f, 0.f};

    // 1-term QK (sweep 1): Qh*Kf over 128 kv cols, distance-4 pairing.
#define COMPUTE_QK1(c, kb) do {                                                \
        _Pragma("unroll")                                                      \
        for (int nt = 0; nt < 16; ++nt) {                                      \
            c[nt][0] = 0.f; c[nt][1] = 0.f; c[nt][2] = 0.f; c[nt][3] = 0.f;    \
        }                                                                      \
        _Pragma("unroll")                                                      \
        for (int ks = 0; ks < 4; ++ks) {                                       \
            _Pragma("unroll")                                                  \
            for (int pp = 0; pp < 4; ++pp) {                                   \
                int row0 = (2 * pp) * 16 + brow;                               \
                int row1 = row0 + 16;                                          \
                uint32_t ad0 = sb + (kb) + row0 * 128 +                        \
                               (((ks * 2 + bch) ^ (row0 & 7)) << 4);           \
                uint32_t ad1 = sb + (kb) + row1 * 128 +                        \
                               (((ks * 2 + bch) ^ (row1 & 7)) << 4);           \
                uint32_t b0[4], b1[4];                                         \
                ldsm4(b0, ad0);                                                \
                ldsm4(b1, ad1);                                                \
                mma16816(c[4*pp+0], aQh[ks], b0[0], b0[1]);                    \
                mma16816(c[4*pp+1], aQh[ks], b0[2], b0[3]);                    \
                mma16816(c[4*pp+2], aQh[ks], b1[0], b1[1]);                    \
                mma16816(c[4*pp+3], aQh[ks], b1[2], b1[3]);                    \
            }                                                                  \
        }                                                                      \
    } while (0)

    // 2-term QK (sweep 2): (Qh + Ql)*Kf over 128 kv cols.
#define COMPUTE_QK2(c, kb) do {                                                \
        _Pragma("unroll")                                                      \
        for (int nt = 0; nt < 16; ++nt) {                                      \
            c[nt][0] = 0.f; c[nt][1] = 0.f; c[nt][2] = 0.f; c[nt][3] = 0.f;    \
        }                                                                      \
        _Pragma("unroll")                                                      \
        for (int ks = 0; ks < 4; ++ks) {                                       \
            _Pragma("unroll")                                                  \
            for (int pp = 0; pp < 4; ++pp) {                                   \
                int row0 = (2 * pp) * 16 + brow;                               \
                int row1 = row0 + 16;                                          \
                uint32_t ad0 = sb + (kb) + row0 * 128 +                        \
                               (((ks * 2 + bch) ^ (row0 & 7)) << 4);           \
                uint32_t ad1 = sb + (kb) + row1 * 128 +                        \
                               (((ks * 2 + bch) ^ (row1 & 7)) << 4);           \
                uint32_t b0[4], b1[4];                                         \
                ldsm4(b0, ad0);                                                \
                ldsm4(b1, ad1);                                                \
                mma16816(c[4*pp+0], aQh[ks], b0[0], b0[1]);                    \
                mma16816(c[4*pp+1], aQh[ks], b0[2], b0[3]);                    \
                mma16816(c[4*pp+2], aQh[ks], b1[0], b1[1]);                    \
                mma16816(c[4*pp+3], aQh[ks], b1[2], b1[3]);                    \
                mma16816(c[4*pp+0], aQl[ks], b0[0], b0[1]);                    \
                mma16816(c[4*pp+1], aQl[ks], b0[2], b0[3]);                    \
                mma16816(c[4*pp+2], aQl[ks], b1[0], b1[1]);                    \
                mma16816(c[4*pp+3], aQl[ks], b1[2], b1[3]);                    \
            }                                                                  \
        }                                                                      \
    } while (0)

    // ================= Sweep 1: sumexp only (fixed offset 0), 16 chunks =================
    for (int u = 0; u < 16; ++u) {
        CP_WAIT0();
        __syncthreads();
        if (u < 15) {
            LOAD_K(SK((u + 1) & 1), u + 1);
            CP_COMMIT();
        }
        if (u == 0) {
#pragma unroll
            for (int ks = 0; ks < 4; ++ks) {
                int row = w * 16 + arow;
                uint32_t ad = sb + SQH + row * 128 + (((ks * 2 + achk) ^ (row & 7)) << 4);
                ldsm4(aQh[ks], ad);
            }
        }
        float c[16][4];
        COMPUTE_QK1(c, SK(u & 1));
#pragma unroll
        for (int h = 0; h < 2; ++h) {
            float sum = 0.f;
#pragma unroll
            for (int nt = 0; nt < 16; ++nt)
                sum += __expf(c[nt][2 * h]) + __expf(c[nt][2 * h + 1]);
            lrun[h] += sum;
        }
    }

    // ---- logZ = log(sum): quad reduce ----
    float* lzs = (float*)(sm + SLZ);
#pragma unroll
    for (int h = 0; h < 2; ++h) {
        float l = lrun[h];
        l += __shfl_xor_sync(0xffffffffu, l, 1);
        l += __shfl_xor_sync(0xffffffffu, l, 2);
        if (qd == 0) lzs[w * 16 + rq + 8 * h] = logf(l);
    }
    __syncwarp();
    const float lz0 = lzs[w * 16 + rq];
    const float lz1 = lzs[w * 16 + rq + 8];

    // ================= Sweep 2: 2-term QK, emit, 2-term PV, 16 chunks =================
    float o[8][4];
#pragma unroll
    for (int g = 0; g < 8; ++g)
#pragma unroll
        for (int j = 0; j < 4; ++j) o[g][j] = 0.f;

    __syncthreads();
    LOAD_K(SK(0), 0);
    LOAD_V(SV(0), 0);
    CP_COMMIT();

    // load Q-lo fragments (Q-hi already resident)
#pragma unroll
    for (int ks = 0; ks < 4; ++ks) {
        int row = w * 16 + arow;
        uint32_t ad = sb + SQL + row * 128 + (((ks * 2 + achk) ^ (row & 7)) << 4);
        ldsm4(aQl[ks], ad);
    }

    float* aRow = attn + ((size_t)(b * LSEQ + qbase + w * 16 + rq)) * LSEQ + qd * 2;
    float* lRow = lattn + ((size_t)(b * LSEQ + qbase + w * 16 + rq)) * LSEQ + qd * 2;

    for (int u = 0; u < 16; ++u) {
        CP_WAIT0();
        __syncthreads();
        if (u < 15) {
            LOAD_K(SK((u + 1) & 1), u + 1);
            LOAD_V(SV((u + 1) & 1), u + 1);
            CP_COMMIT();
        }

        float c[16][4];
        COMPUTE_QK2(c, SK(u & 1));

        // convert: attn/lattn stores + register-resident P fragments (128 cols)
        uint32_t aPh[8][4], aPl[8][4];
        float* aT = aRow + u * 128;
        float* lT = lRow + u * 128;
#pragma unroll
        for (int kc = 0; kc < 8; ++kc) {
#pragma unroll
            for (int qq = 0; qq < 2; ++qq) {
                const int nt = 2 * kc + qq;
                float la0 = c[nt][0] - lz0, la1 = c[nt][1] - lz0;
                float la2 = c[nt][2] - lz1, la3 = c[nt][3] - lz1;
                float p0 = __expf(la0), p1 = __expf(la1);
                float p2 = __expf(la2), p3 = __expf(la3);
                *(float2*)(aT + nt * 8) = make_float2(p0, p1);
                *(float2*)(aT + 8 * LSEQ + nt * 8) = make_float2(p2, p3);
                *(float2*)(lT + nt * 8) = make_float2(la0, la1);
                *(float2*)(lT + 8 * LSEQ + nt * 8) = make_float2(la2, la3);
                __half h0 = __float2half_rn(p0), h1 = __float2half_rn(p1);
                __half h2 = __float2half_rn(p2), h3 = __float2half_rn(p3);
                __half2 H01 = __halves2half2(h0, h1), H23 = __halves2half2(h2, h3);
                aPh[kc][qq * 2 + 0] = *reinterpret_cast<uint32_t*>(&H01);
                aPh[kc][qq * 2 + 1] = *reinterpret_cast<uint32_t*>(&H23);
                __half2 L01 = __halves2half2(__float2half_rn(p0 - __half2float(h0)),
                                             __float2half_rn(p1 - __half2float(h1)));
                __half2 L23 = __halves2half2(__float2half_rn(p2 - __half2float(h2)),
                                             __float2half_rn(p3 - __half2float(h3)));
                aPl[kc][qq * 2 + 0] = *reinterpret_cast<uint32_t*>(&L01);
                aPl[kc][qq * 2 + 1] = *reinterpret_cast<uint32_t*>(&L23);
            }
        }

        // 2-term PV over 128 kv: O += (Ph + Pl) * Vf   (V rows = d, 256B rows)
        const uint32_t vb = sb + SV(u & 1);
#pragma unroll
        for (int kc = 0; kc < 8; ++kc) {
#pragma unroll
            for (int gg = 0; gg < 2; ++gg) {
                int row0 = gg * 32 + brow;     // d rows
                int row1 = row0 + 16;
                uint32_t ad0 = vb + row0 * 256 + (((kc * 2 + bch) ^ (row0 & 15)) << 4);
                uint32_t ad1 = vb + row1 * 256 + (((kc * 2 + bch) ^ (row1 & 15)) << 4);
                uint32_t v0[4], v1[4];
                ldsm4(v0, ad0);
                ldsm4(v1, ad1);
                mma16816(o[4*gg+0], aPh[kc], v0[0], v0[1]);
                mma16816(o[4*gg+1], aPh[kc], v0[2], v0[3]);
                mma16816(o[4*gg+2], aPh[kc], v1[0], v1[1]);
                mma16816(o[4*gg+3], aPh[kc], v1[2], v1[3]);
                mma16816(o[4*gg+0], aPl[kc], v0[0], v0[1]);
                mma16816(o[4*gg+1], aPl[kc], v0[2], v0[3]);
                mma16816(o[4*gg+2], aPl[kc], v1[0], v1[1]);
                mma16816(o[4*gg+3], aPl[kc], v1[2], v1[3]);
            }
        }
    }

    // ---- head-folded output ----
    {
        int qr = qbase + w * 16 + rq;
        float* dp = outp + (size_t)qr * (DH * BH) + b * DH + qd * 2;
#pragma unroll
        for (int g = 0; g < 8; ++g) {
            *(float2*)(dp + g * 8) = make_float2(o[g][0], o[g][1]);
            *(float2*)(dp + 8 * (DH * BH) + g * 8) = make_float2(o[g][2], o[g][3]);
        }
    }
}

extern "C" void kernel_launch(void* const* d_in, const int* in_sizes, int n_in,
                              void* d_out, int out_size) {
    const float* q = (const float*)d_in[0];
    const float* k = (const float*)d_in[1];
    const float* v = (const float*)d_in[2];

    float* outp = (float*)d_out;
    float* attn = outp + OUT_ELE;
    float* lattn = attn + ATT_ELE;

    cudaFuncSetAttribute(sdpa_fused, cudaFuncAttributeMaxDynamicSharedMemorySize, SMEM_TOT);

    prep_q<<<2048, 256>>>(q);
    prep_k<<<2048, 256>>>(k);
    prep_v<<<256, 256>>>(v);

    dim3 grid(LSEQ / 64, BH);
    sdpa_fused<<<grid, 128, SMEM_TOT>>>(attn, lattn, outp);
}

// round 16
// speedup vs baseline: 1.7631x; 1.0237x over previous
#include <cuda_runtime.h>
#include <cuda_fp16.h>
#include <cstdint>
#include <math.h>

#define BH 16
#define LSEQ 2048
#define DH 64
#define OUT_ELE (LSEQ * DH * BH)
#define ATT_ELE ((size_t)BH * LSEQ * LSEQ)

__device__ __half g_Qh[BH * LSEQ * DH];
__device__ __half g_Ql[BH * LSEQ * DH];
__device__ __half g_Kf[BH * LSEQ * DH];
__device__ __half g_Vtf[BH * DH * LSEQ];

__device__ __forceinline__ uint32_t smem_u32(const void* p) {
    uint32_t a;
    asm("{ .reg .u64 t; cvta.to.shared.u64 t, %1; cvt.u32.u64 %0, t; }" : "=r"(a) : "l"(p));
    return a;
}
__device__ __forceinline__ void ldsm4(uint32_t* r, uint32_t addr) {
    asm volatile("ldmatrix.sync.aligned.m8n8.x4.shared.b16 {%0,%1,%2,%3}, [%4];"
                 : "=r"(r[0]), "=r"(r[1]), "=r"(r[2]), "=r"(r[3]) : "r"(addr));
}
__device__ __forceinline__ void mma16816(float* c, const uint32_t* a, uint32_t b0, uint32_t b1) {
    asm("mma.sync.aligned.m16n8k16.row.col.f32.f16.f16.f32 "
        "{%0,%1,%2,%3}, {%4,%5,%6,%7}, {%8,%9}, {%0,%1,%2,%3};"
        : "+f"(c[0]), "+f"(c[1]), "+f"(c[2]), "+f"(c[3])
        : "r"(a[0]), "r"(a[1]), "r"(a[2]), "r"(a[3]), "r"(b0), "r"(b1));
}
__device__ __forceinline__ void split2h(float a, float b, uint32_t& hi, uint32_t& lo) {
    __half ah = __float2half_rn(a), bh = __float2half_rn(b);
    __half al = __float2half_rn(a - __half2float(ah));
    __half bl = __float2half_rn(b - __half2float(bh));
    __half2 H = __halves2half2(ah, bh);
    __half2 L = __halves2half2(al, bl);
    hi = *reinterpret_cast<uint32_t*>(&H);
    lo = *reinterpret_cast<uint32_t*>(&L);
}
__device__ __forceinline__ uint32_t pack2h(float a, float b) {
    __half2 H = __halves2half2(__float2half_rn(a), __float2half_rn(b));
    return *reinterpret_cast<uint32_t*>(&H);
}
__device__ __forceinline__ void cpasync16(uint32_t dst, const void* src) {
    asm volatile("cp.async.cg.shared.global [%0], [%1], 16;" :: "r"(dst), "l"(src));
}
#define CP_COMMIT() asm volatile("cp.async.commit_group;" ::: "memory")
#define CP_WAIT0()  asm volatile("cp.async.wait_group 0;" ::: "memory")

// 2 exps per MUFU via ex2.approx.f16x2 (sweep-1 stats only; outputs use fp32 exp)
__device__ __forceinline__ float exp2sum_h2(float a, float b) {
    __half2 h = __floats2half2_rn(a * 1.44269504f, b * 1.44269504f);
    uint32_t u = *reinterpret_cast<uint32_t*>(&h);
    uint32_t r;
    asm("ex2.approx.f16x2 %0, %1;" : "=r"(r) : "r"(u));
    __half2 e = *reinterpret_cast<__half2*>(&r);
    float2 f = __half22float2(e);
    return f.x + f.y;
}

// ---------------- Prepass ----------------
__global__ void prep_qk(const float* __restrict__ q, const float* __restrict__ k) {
    int blk = blockIdx.x;
    int idx = (blk & 2047) * 256 + threadIdx.x;
    if (blk < 2048) {
        float4 x = ((const float4*)q)[idx];
        x.x *= 0.125f; x.y *= 0.125f; x.z *= 0.125f; x.w *= 0.125f;
        uint32_t h0, l0, h1, l1;
        split2h(x.x, x.y, h0, l0);
        split2h(x.z, x.w, h1, l1);
        ((uint2*)g_Qh)[idx] = make_uint2(h0, h1);
        ((uint2*)g_Ql)[idx] = make_uint2(l0, l1);
    } else {
        float4 x = ((const float4*)k)[idx];
        ((uint2*)g_Kf)[idx] = make_uint2(pack2h(x.x, x.y), pack2h(x.z, x.w));
    }
}
__global__ void prep_v(const float* __restrict__ v) {
    __shared__ float vs[128 * 65];
    const int b = blockIdx.x >> 4, st = blockIdx.x & 15, tid = threadIdx.x;
    const float4* vp = (const float4*)(v + ((size_t)(b * LSEQ + st * 128)) * DH);
#pragma unroll
    for (int it = 0; it < 8; ++it) {
        int fi = it * 256 + tid;
        int s = fi >> 4, d4 = fi & 15;
        float4 x = vp[fi];
        vs[s * 65 + d4 * 4 + 0] = x.x;
        vs[s * 65 + d4 * 4 + 1] = x.y;
        vs[s * 65 + d4 * 4 + 2] = x.z;
        vs[s * 65 + d4 * 4 + 3] = x.w;
    }
    __syncthreads();
#pragma unroll
    for (int it = 0; it < 4; ++it) {
        int fo = it * 256 + tid;
        int d = fo >> 4, cu = fo & 15;
        uint32_t hw[4];
#pragma unroll
        for (int j = 0; j < 4; ++j)
            hw[j] = pack2h(vs[(cu * 8 + 2 * j) * 65 + d], vs[(cu * 8 + 2 * j + 1) * 65 + d]);
        size_t o = ((size_t)(b * DH + d)) * LSEQ + st * 128 + cu * 8;
        *(uint4*)(g_Vtf + o) = make_uint4(hw[0], hw[1], hw[2], hw[3]);
    }
}

// ---------------- Fused attention (128 threads, 4 warps, 64 q-rows/CTA) ----------------
#define SQH 0
#define SQL 8192
#define SK(i) (16384 + (i) * 16384)
#define SV(i) (49152 + (i) * 16384)
#define SLZ 81920
#define SMEM_TOT 82432

__global__ void __launch_bounds__(128, 2)
sdpa_fused(float* __restrict__ attn, float* __restrict__ lattn, float* __restrict__ outp) {
    extern __shared__ char sm[];
    const uint32_t sb = smem_u32(sm);
    const int tid = threadIdx.x, lane = tid & 31, w = tid >> 5;   // w in 0..3
    const int b = blockIdx.y, qbase = blockIdx.x * 64;

    const int arow = lane & 15, achk = lane >> 4;
    const int brow = ((lane >> 4) << 3) + (lane & 7), bch = (lane >> 3) & 1;
    const int rq = lane >> 2, qd = lane & 3;

    const char* kf_base = (const char*)(g_Kf + (size_t)b * LSEQ * DH);
    const char* vf_base = (const char*)(g_Vtf + (size_t)b * DH * LSEQ);

#define LOAD_K(buf, u) do {                                                    \
        const char* _s = kf_base + (size_t)(u) * 16384;                        \
        _Pragma("unroll")                                                      \
        for (int r = 0; r < 8; ++r) {                                          \
            int fo = r * 128 + tid;                                            \
            int row = fo >> 3, cu = fo & 7;                                    \
            uint32_t off = (uint32_t)row * 128 + ((cu ^ (row & 7)) << 4);      \
            cpasync16(sb + (buf) + off, _s + fo * 16);                         \
        }                                                                      \
    } while (0)

#define LOAD_V(buf, u) do {                                                    \
        _Pragma("unroll")                                                      \
        for (int r = 0; r < 8; ++r) {                                          \
            int fo = r * 128 + tid;                                            \
            int row = fo >> 4, cu = fo & 15;                                   \
            uint32_t off = (uint32_t)row * 256 + ((cu ^ (row & 15)) << 4);     \
            size_t sof = (size_t)row * (LSEQ * 2) + (size_t)(u) * 256 + cu * 16; \
            cpasync16(sb + (buf) + off, vf_base + sof);                        \
        }                                                                      \
    } while (0)

    // ---- prologue: Q tile (64x64, hi+lo) + K chunk 0 ----
    {
        const char* qh = (const char*)(g_Qh + (size_t)(b * LSEQ + qbase) * DH);
        const char* ql = (const char*)(g_Ql + (size_t)(b * LSEQ + qbase) * DH);
#pragma unroll
        for (int r = 0; r < 4; ++r) {
            int fo = r * 128 + tid;
            int row = fo >> 3, cu = fo & 7;
            uint32_t off = (uint32_t)row * 128 + ((cu ^ (row & 7)) << 4);
            cpasync16(sb + SQH + off, qh + fo * 16);
            cpasync16(sb + SQL + off, ql + fo * 16);
        }
        LOAD_K(SK(0), 0);
        CP_COMMIT();
    }

    uint32_t aQh[4][4], aQl[4][4];
    float lrun[2] = {0.f, 0.f};

#define COMPUTE_QK1(c, kb) do {                                                \
        _Pragma("unroll")                                                      \
        for (int nt = 0; nt < 16; ++nt) {                                      \
            c[nt][0] = 0.f; c[nt][1] = 0.f; c[nt][2] = 0.f; c[nt][3] = 0.f;    \
        }                                                                      \
        _Pragma("unroll")                                                      \
        for (int ks = 0; ks < 4; ++ks) {                                       \
            _Pragma("unroll")                                                  \
            for (int pp = 0; pp < 4; ++pp) {                                   \
                int row0 = (2 * pp) * 16 + brow;                               \
                int row1 = row0 + 16;                                          \
                uint32_t ad0 = sb + (kb) + row0 * 128 +                        \
                               (((ks * 2 + bch) ^ (row0 & 7)) << 4);           \
                uint32_t ad1 = sb + (kb) + row1 * 128 +                        \
                               (((ks * 2 + bch) ^ (row1 & 7)) << 4);           \
                uint32_t b0[4], b1[4];                                         \
                ldsm4(b0, ad0);                                                \
                ldsm4(b1, ad1);                                                \
                mma16816(c[4*pp+0], aQh[ks], b0[0], b0[1]);                    \
                mma16816(c[4*pp+1], aQh[ks], b0[2], b0[3]);                    \
                mma16816(c[4*pp+2], aQh[ks], b1[0], b1[1]);                    \
                mma16816(c[4*pp+3], aQh[ks], b1[2], b1[3]);                    \
            }                                                                  \
        }                                                                      \
    } while (0)

#define COMPUTE_QK2(c, kb) do {                                                \
        _Pragma("unroll")                                                      \
        for (int nt = 0; nt < 16; ++nt) {                                      \
            c[nt][0] = 0.f; c[nt][1] = 0.f; c[nt][2] = 0.f; c[nt][3] = 0.f;    \
        }                                                                      \
        _Pragma("unroll")                                                      \
        for (int ks = 0; ks < 4; ++ks) {                                       \
            _Pragma("unroll")                                                  \
            for (int pp = 0; pp < 4; ++pp) {                                   \
                int row0 = (2 * pp) * 16 + brow;                               \
                int row1 = row0 + 16;                                          \
                uint32_t ad0 = sb + (kb) + row0 * 128 +                        \
                               (((ks * 2 + bch) ^ (row0 & 7)) << 4);           \
                uint32_t ad1 = sb + (kb) + row1 * 128 +                        \
                               (((ks * 2 + bch) ^ (row1 & 7)) << 4);           \
                uint32_t b0[4], b1[4];                                         \
                ldsm4(b0, ad0);                                                \
                ldsm4(b1, ad1);                                                \
                mma16816(c[4*pp+0], aQh[ks], b0[0], b0[1]);                    \
                mma16816(c[4*pp+1], aQh[ks], b0[2], b0[3]);                    \
                mma16816(c[4*pp+2], aQh[ks], b1[0], b1[1]);                    \
                mma16816(c[4*pp+3], aQh[ks], b1[2], b1[3]);                    \
                mma16816(c[4*pp+0], aQl[ks], b0[0], b0[1]);                    \
                mma16816(c[4*pp+1], aQl[ks], b0[2], b0[3]);                    \
                mma16816(c[4*pp+2], aQl[ks], b1[0], b1[1]);                    \
                mma16816(c[4*pp+3], aQl[ks], b1[2], b1[3]);                    \
            }                                                                  \
        }                                                                      \
    } while (0)

    // ================= Sweep 1: sumexp (f16x2 ex2), 16 chunks =================
    for (int u = 0; u < 16; ++u) {
        CP_WAIT0();
        __syncthreads();
        if (u < 15) {
            LOAD_K(SK((u + 1) & 1), u + 1);
            CP_COMMIT();
        }
        if (u == 0) {
#pragma unroll
            for (int ks = 0; ks < 4; ++ks) {
                int row = w * 16 + arow;
                uint32_t ad = sb + SQH + row * 128 + (((ks * 2 + achk) ^ (row & 7)) << 4);
                ldsm4(aQh[ks], ad);
            }
        }
        float c[16][4];
        COMPUTE_QK1(c, SK(u & 1));
#pragma unroll
        for (int h = 0; h < 2; ++h) {
            float sum = 0.f;
#pragma unroll
            for (int nt = 0; nt < 16; ++nt)
                sum += exp2sum_h2(c[nt][2 * h], c[nt][2 * h + 1]);
            lrun[h] += sum;
        }
    }

    // ---- logZ = log(sum): quad reduce ----
    float* lzs = (float*)(sm + SLZ);
#pragma unroll
    for (int h = 0; h < 2; ++h) {
        float l = lrun[h];
        l += __shfl_xor_sync(0xffffffffu, l, 1);
        l += __shfl_xor_sync(0xffffffffu, l, 2);
        if (qd == 0) lzs[w * 16 + rq + 8 * h] = logf(l);
    }
    __syncwarp();
    const float lz0 = lzs[w * 16 + rq];
    const float lz1 = lzs[w * 16 + rq + 8];

    // ================= Sweep 2: 2-term QK, emit, 2-term PV, 16 chunks =================
    float o[8][4];
#pragma unroll
    for (int g = 0; g < 8; ++g)
#pragma unroll
        for (int j = 0; j < 4; ++j) o[g][j] = 0.f;

    __syncthreads();
    LOAD_K(SK(0), 0);
    LOAD_V(SV(0), 0);
    CP_COMMIT();

#pragma unroll
    for (int ks = 0; ks < 4; ++ks) {
        int row = w * 16 + arow;
        uint32_t ad = sb + SQL + row * 128 + (((ks * 2 + achk) ^ (row & 7)) << 4);
        ldsm4(aQl[ks], ad);
    }

    float* aRow = attn + ((size_t)(b * LSEQ + qbase + w * 16 + rq)) * LSEQ + qd * 2;
    float* lRow = lattn + ((size_t)(b * LSEQ + qbase + w * 16 + rq)) * LSEQ + qd * 2;

    for (int u = 0; u < 16; ++u) {
        CP_WAIT0();
        __syncthreads();
        if (u < 15) {
            LOAD_K(SK((u + 1) & 1), u + 1);
            LOAD_V(SV((u + 1) & 1), u + 1);
            CP_COMMIT();
        }

        float c[16][4];
        COMPUTE_QK2(c, SK(u & 1));

        uint32_t aPh[8][4], aPl[8][4];
        float* aT = aRow + u * 128;
        float* lT = lRow + u * 128;
#pragma unroll
        for (int kc = 0; kc < 8; ++kc) {
#pragma unroll
            for (int qq = 0; qq < 2; ++qq) {
                const int nt = 2 * kc + qq;
                float la0 = c[nt][0] - lz0, la1 = c[nt][1] - lz0;
                float la2 = c[nt][2] - lz1, la3 = c[nt][3] - lz1;
                float p0 = __expf(la0), p1 = __expf(la1);
                float p2 = __expf(la2), p3 = __expf(la3);
                *(float2*)(aT + nt * 8) = make_float2(p0, p1);
                *(float2*)(aT + 8 * LSEQ + nt * 8) = make_float2(p2, p3);
                *(float2*)(lT + nt * 8) = make_float2(la0, la1);
                *(float2*)(lT + 8 * LSEQ + nt * 8) = make_float2(la2, la3);
                __half h0 = __float2half_rn(p0), h1 = __float2half_rn(p1);
                __half h2 = __float2half_rn(p2), h3 = __float2half_rn(p3);
                __half2 H01 = __halves2half2(h0, h1), H23 = __halves2half2(h2, h3);
                aPh[kc][qq * 2 + 0] = *reinterpret_cast<uint32_t*>(&H01);
                aPh[kc][qq * 2 + 1] = *reinterpret_cast<uint32_t*>(&H23);
                __half2 L01 = __halves2half2(__float2half_rn(p0 - __half2float(h0)),
                                             __float2half_rn(p1 - __half2float(h1)));
                __half2 L23 = __halves2half2(__float2half_rn(p2 - __half2float(h2)),
                                             __float2half_rn(p3 - __half2float(h3)));
                aPl[kc][qq * 2 + 0] = *reinterpret_cast<uint32_t*>(&L01);
                aPl[kc][qq * 2 + 1] = *reinterpret_cast<uint32_t*>(&L23);
            }
        }

        const uint32_t vb = sb + SV(u & 1);
#pragma unroll
        for (int kc = 0; kc < 8; ++kc) {
#pragma unroll
            for (int gg = 0; gg < 2; ++gg) {
                int row0 = gg * 32 + brow;
                int row1 = row0 + 16;
                uint32_t ad0 = vb + row0 * 256 + (((kc * 2 + bch) ^ (row0 & 15)) << 4);
                uint32_t ad1 = vb + row1 * 256 + (((kc * 2 + bch) ^ (row1 & 15)) << 4);
                uint32_t v0[4], v1[4];
                ldsm4(v0, ad0);
                ldsm4(v1, ad1);
                mma16816(o[4*gg+0], aPh[kc], v0[0], v0[1]);
                mma16816(o[4*gg+1], aPh[kc], v0[2], v0[3]);
                mma16816(o[4*gg+2], aPh[kc], v1[0], v1[1]);
                mma16816(o[4*gg+3], aPh[kc], v1[2], v1[3]);
                mma16816(o[4*gg+0], aPl[kc], v0[0], v0[1]);
                mma16816(o[4*gg+1], aPl[kc], v0[2], v0[3]);
                mma16816(o[4*gg+2], aPl[kc], v1[0], v1[1]);
                mma16816(o[4*gg+3], aPl[kc], v1[2], v1[3]);
            }
        }
    }

    // ---- head-folded output ----
    {
        int qr = qbase + w * 16 + rq;
        float* dp = outp + (size_t)qr * (DH * BH) + b * DH + qd * 2;
#pragma unroll
        for (int g = 0; g < 8; ++g) {
            *(float2*)(dp + g * 8) = make_float2(o[g][0], o[g][1]);
            *(float2*)(dp + 8 * (DH * BH) + g * 8) = make_float2(o[g][2], o[g][3]);
        }
    }
}

extern "C" void kernel_launch(void* const* d_in, const int* in_sizes, int n_in,
                              void* d_out, int out_size) {
    const float* q = (const float*)d_in[0];
    const float* k = (const float*)d_in[1];
    const float* v = (const float*)d_in[2];

    float* outp = (float*)d_out;
    float* attn = outp + OUT_ELE;
    float* lattn = attn + ATT_ELE;

    cudaFuncSetAttribute(sdpa_fused, cudaFuncAttributeMaxDynamicSharedMemorySize, SMEM_TOT);

    prep_qk<<<4096, 256>>>(q, k);
    prep_v<<<256, 256>>>(v);

    dim3 grid(LSEQ / 64, BH);
    sdpa_fused<<<grid, 128, SMEM_TOT>>>(attn, lattn, outp);
}